// round 10
// baseline (speedup 1.0000x reference)
#include <cuda_runtime.h>
#include <cuda_fp16.h>
#include <math.h>
#include <stdint.h>

// Problem dims (fixed)
#define NT 8192   // tokens
#define NH 1024   // hidden
#define NE 8      // experts
#define NI 1408   // intermediate

#define KC 64     // K halfs per pipeline stage
#define NSTAGE 4
#define PADH 72   // halfs per smem row (144B: ldmatrix row banks conflict-free)

// gateup stage (halfs): A[128][72] + Bg[128][72] + Bu[128][72]
#define GU_BG_OFF (128 * PADH)
#define GU_BU_OFF (256 * PADH)
#define GU_STAGE  (384 * PADH)
#define GU_SMEM_BYTES (NSTAGE * GU_STAGE * 2)        // 221184

// down stage (halfs): A[128][72] + B[256][72]
#define DN_B_OFF  (128 * PADH)
#define DN_STAGE  (384 * PADH)
#define DN_SMEM_BYTES (NSTAGE * DN_STAGE * 2)        // 221184

// ---------------- scratch (device globals) ----------------------------------
__device__ __half g_xh [(size_t)NT*NH];
__device__ __half g_egT[(size_t)NE*NI*NH];       // fp16 weights, [N][K]
__device__ __half g_euT[(size_t)NE*NI*NH];
__device__ __half g_edT[(size_t)NE*NH*NI];
__device__ __half g_sgT[(size_t)NI*NH];
__device__ __half g_suT[(size_t)NI*NH];
__device__ __half g_sdT[(size_t)NH*NI];
__device__ __half g_hbuf[(size_t)NE*NT*NI];
__device__ __half g_shh [(size_t)NT*NI];
__device__ float  g_down[(size_t)2*NT*NH];
__device__ int    g_rowlist[NE*NT];
__device__ int    g_pidlist[NE*NT];
__device__ int    g_cnt[NE];
__device__ float  g_w[NT*2];

// ---------------- helpers ----------------------------------------------------
__device__ __forceinline__ uint32_t smem_u32(const void* p) {
    uint32_t a;
    asm("{ .reg .u64 t; cvta.to.shared.u64 t, %1; cvt.u32.u64 %0, t; }" : "=r"(a) : "l"(p));
    return a;
}
__device__ __forceinline__ void cpa16(uint32_t dst, const void* src) {
    asm volatile("cp.async.cg.shared.global [%0], [%1], 16;" :: "r"(dst), "l"(src) : "memory");
}
__device__ __forceinline__ void cp_commit() {
    asm volatile("cp.async.commit_group;" ::: "memory");
}
__device__ __forceinline__ void mma_f16(float* c, const uint32_t* a, const uint32_t* b) {
    asm volatile(
        "mma.sync.aligned.m16n8k16.row.col.f32.f16.f16.f32 "
        "{%0,%1,%2,%3}, {%4,%5,%6,%7}, {%8,%9}, {%0,%1,%2,%3};"
        : "+f"(c[0]), "+f"(c[1]), "+f"(c[2]), "+f"(c[3])
        : "r"(a[0]), "r"(a[1]), "r"(a[2]), "r"(a[3]), "r"(b[0]), "r"(b[1]));
}
__device__ __forceinline__ void ldsm4(uint32_t addr, uint32_t& r0, uint32_t& r1,
                                      uint32_t& r2, uint32_t& r3) {
    asm volatile("ldmatrix.sync.aligned.m8n8.x4.shared.b16 {%0,%1,%2,%3}, [%4];"
                 : "=r"(r0), "=r"(r1), "=r"(r2), "=r"(r3) : "r"(addr));
}

// ---------------- small kernels ----------------------------------------------
__global__ void zero_cnt_kernel() {
    if (threadIdx.x < NE) g_cnt[threadIdx.x] = 0;
}

__global__ void cvt_kernel(const float* __restrict__ in, __half* __restrict__ out, int n4) {
    int i = blockIdx.x * blockDim.x + threadIdx.x;
    int stride = gridDim.x * blockDim.x;
    for (; i < n4; i += stride) {
        float4 v = reinterpret_cast<const float4*>(in)[i];
        __half2 lo = __floats2half2_rn(v.x, v.y);
        __half2 hi = __floats2half2_rn(v.z, v.w);
        uint2 pk = make_uint2(*reinterpret_cast<uint32_t*>(&lo),
                              *reinterpret_cast<uint32_t*>(&hi));
        reinterpret_cast<uint2*>(out)[i] = pk;
    }
}

// [R][C] f32 -> [C][R] f16; 64(R) x 32(C) tiles, half2 stores
__global__ void transcvt_kernel(const float* __restrict__ in, __half* __restrict__ out,
                                int R, int C) {
    __shared__ float tile[32][65];   // [c][r]
    size_t boff = (size_t)blockIdx.z * R * C;
    const float* ib = in + boff;
    __half* ob = out + boff;
    int c0 = blockIdx.x * 32, r0 = blockIdx.y * 64;
    int tx = threadIdx.x, ty = threadIdx.y;
    #pragma unroll
    for (int i = 0; i < 8; i++) {
        int r = ty + 8*i;
        tile[tx][r] = ib[(size_t)(r0 + r) * C + c0 + tx];
    }
    __syncthreads();
    #pragma unroll
    for (int ic = 0; ic < 4; ic++) {
        int c = ty + 8*ic;
        __half2 v = __floats2half2_rn(tile[c][2*tx], tile[c][2*tx+1]);
        *reinterpret_cast<__half2*>(ob + (size_t)(c0 + c) * R + r0 + 2*tx) = v;
    }
}

// ---------------- router ------------------------------------------------------
__global__ void router_kernel(const float* __restrict__ x,
                              const float* __restrict__ gw) {
    int gtid = blockIdx.x * blockDim.x + threadIdx.x;
    int t    = gtid >> 5;
    int lane = gtid & 31;
    if (t >= NT) return;
    const float* xr = x + (size_t)t * NH;

    float acc[8] = {0.f,0.f,0.f,0.f,0.f,0.f,0.f,0.f};
    for (int h = lane; h < NH; h += 32) {
        float xv = __ldg(xr + h);
        const float4* g4 = reinterpret_cast<const float4*>(gw + (size_t)h * 8);
        float4 a = __ldg(g4 + 0);
        float4 b = __ldg(g4 + 1);
        acc[0] = fmaf(xv, a.x, acc[0]); acc[1] = fmaf(xv, a.y, acc[1]);
        acc[2] = fmaf(xv, a.z, acc[2]); acc[3] = fmaf(xv, a.w, acc[3]);
        acc[4] = fmaf(xv, b.x, acc[4]); acc[5] = fmaf(xv, b.y, acc[5]);
        acc[6] = fmaf(xv, b.z, acc[6]); acc[7] = fmaf(xv, b.w, acc[7]);
    }
    #pragma unroll
    for (int e = 0; e < 8; e++)
        #pragma unroll
        for (int off = 16; off > 0; off >>= 1)
            acc[e] += __shfl_xor_sync(0xffffffffu, acc[e], off);
    if (lane == 0) {
        float m = acc[0];
        #pragma unroll
        for (int e = 1; e < 8; e++) m = fmaxf(m, acc[e]);
        float p[8], s = 0.f;
        #pragma unroll
        for (int e = 0; e < 8; e++) { p[e] = expf(acc[e] - m); s += p[e]; }
        float inv = 1.f / s;
        #pragma unroll
        for (int e = 0; e < 8; e++) p[e] *= inv;
        int i0 = 0; float v0 = p[0];
        #pragma unroll
        for (int e = 1; e < 8; e++) if (p[e] > v0) { v0 = p[e]; i0 = e; }
        int i1 = -1; float v1 = -1.f;
        #pragma unroll
        for (int e = 0; e < 8; e++) if (e != i0 && p[e] > v1) { v1 = p[e]; i1 = e; }
        float denom = v0 + v1 + 1e-6f;
        g_w[2*t]   = v0 / denom;
        g_w[2*t+1] = v1 / denom;
        int r0 = atomicAdd(&g_cnt[i0], 1);
        g_rowlist[i0*NT + r0] = t; g_pidlist[i0*NT + r0] = 2*t;
        int r1 = atomicAdd(&g_cnt[i1], 1);
        g_rowlist[i1*NT + r1] = t; g_pidlist[i1*NT + r1] = 2*t + 1;
    }
}

// ---------------- gate+up SwiGLU GEMM (fp16 mma + ldmatrix) --------------------
// Block 128(M) x 128(N per matrix). 8 warps, warp tile 64x32 per matrix.
template<bool EXPERT>
__global__ __launch_bounds__(256, 1)
void gateup_mma(const __half* __restrict__ WgT,   // [*, NI, NH] k-contig
                const __half* __restrict__ WuT) {
    extern __shared__ __align__(16) char dsm[];
    const int e    = EXPERT ? blockIdx.z : 0;
    const int M    = EXPERT ? g_cnt[e] : NT;
    const int row0 = blockIdx.y * 128;
    if (row0 >= M) return;
    const int col0 = blockIdx.x * 128;

    const __half* wg = WgT + (EXPERT ? (size_t)e * NI * NH : (size_t)0);
    const __half* wu = WuT + (EXPERT ? (size_t)e * NI * NH : (size_t)0);
    __half* Hout = EXPERT ? (g_hbuf + (size_t)e * NT * NI) : g_shh;

    const int tid = threadIdx.x, wid = tid >> 5, lane = tid & 31;
    const uint32_t sbase = smem_u32(dsm);

    // copy roles
    const __half* s0; const __half* s1;
    uint32_t d0, d1;
    if (tid < 128) {
        int r = tid;
        int li = row0 + r; if (li >= M) li = M - 1;
        int gr = EXPERT ? g_rowlist[e*NT + li] : li;
        s0 = s1 = g_xh + (size_t)gr * NH;
        d0 = d1 = (uint32_t)r * PADH;
    } else if (tid < 192) {
        int u = tid - 128;
        s0 = wg + (size_t)(col0 + u)      * NH;
        s1 = wg + (size_t)(col0 + u + 64) * NH;
        d0 = GU_BG_OFF + (uint32_t)u * PADH;
        d1 = GU_BG_OFF + (uint32_t)(u + 64) * PADH;
    } else {
        int u = tid - 192;
        s0 = wu + (size_t)(col0 + u)      * NH;
        s1 = wu + (size_t)(col0 + u + 64) * NH;
        d0 = GU_BU_OFF + (uint32_t)u * PADH;
        d1 = GU_BU_OFF + (uint32_t)(u + 64) * PADH;
    }
    const bool tworow = (tid >= 128);

    float accg[4][4][4], accu[4][4][4];
    #pragma unroll
    for (int i = 0; i < 4; i++)
        #pragma unroll
        for (int j = 0; j < 4; j++)
            #pragma unroll
            for (int q = 0; q < 4; q++) { accg[i][j][q] = 0.f; accu[i][j][q] = 0.f; }

    const int m0 = (wid & 1) * 64, n0 = (wid >> 1) * 32;
    const int tg = lane >> 2, ti = lane & 3;

    const int q8 = lane >> 3, l7 = lane & 7;
    const uint32_t aoff  = (uint32_t)((m0 + (q8 & 1)*8 + l7) * PADH + (q8 >> 1)*8) * 2;
    const uint32_t bgoff = (uint32_t)(GU_BG_OFF + (n0 + (q8 >> 1)*8 + l7) * PADH + (q8 & 1)*8) * 2;
    const uint32_t buoff = (uint32_t)(GU_BU_OFF + (n0 + (q8 >> 1)*8 + l7) * PADH + (q8 & 1)*8) * 2;

    int koff = 0;
    #pragma unroll
    for (int s = 0; s < NSTAGE - 1; s++) {
        uint32_t base = sbase + (uint32_t)(s * GU_STAGE) * 2;
        #pragma unroll
        for (int c = 0; c < 8; c++) cpa16(base + d0*2 + c*16, s0 + koff + c*8);
        if (tworow) {
            #pragma unroll
            for (int c = 0; c < 8; c++) cpa16(base + d1*2 + c*16, s1 + koff + c*8);
        }
        cp_commit();
        koff += KC;
    }

    const int KST = NH / KC;   // 16
    for (int j = 0; j < KST; j++) {
        if      (j < KST - 2) asm volatile("cp.async.wait_group 2;" ::: "memory");
        else if (j < KST - 1) asm volatile("cp.async.wait_group 1;" ::: "memory");
        else                  asm volatile("cp.async.wait_group 0;" ::: "memory");
        __syncthreads();
        if (j + NSTAGE - 1 < KST) {
            int s = (j + NSTAGE - 1) % NSTAGE;
            uint32_t base = sbase + (uint32_t)(s * GU_STAGE) * 2;
            #pragma unroll
            for (int c = 0; c < 8; c++) cpa16(base + d0*2 + c*16, s0 + koff + c*8);
            if (tworow) {
                #pragma unroll
                for (int c = 0; c < 8; c++) cpa16(base + d1*2 + c*16, s1 + koff + c*8);
            }
            cp_commit();
            koff += KC;
        }
        const uint32_t stg = sbase + (uint32_t)((j % NSTAGE) * GU_STAGE) * 2;
        #pragma unroll
        for (int kk = 0; kk < 4; kk++) {
            const uint32_t kb = (uint32_t)(kk * 16) * 2;
            uint32_t a[4][4];
            #pragma unroll
            for (int i = 0; i < 4; i++)
                ldsm4(stg + aoff + (uint32_t)(i*16*PADH)*2 + kb,
                      a[i][0], a[i][1], a[i][2], a[i][3]);
            uint32_t bg[4][2], bu[4][2];
            #pragma unroll
            for (int jp = 0; jp < 2; jp++) {
                ldsm4(stg + bgoff + (uint32_t)(jp*16*PADH)*2 + kb,
                      bg[2*jp][0], bg[2*jp][1], bg[2*jp+1][0], bg[2*jp+1][1]);
                ldsm4(stg + buoff + (uint32_t)(jp*16*PADH)*2 + kb,
                      bu[2*jp][0], bu[2*jp][1], bu[2*jp+1][0], bu[2*jp+1][1]);
            }
            #pragma unroll
            for (int jn = 0; jn < 4; jn++)
                #pragma unroll
                for (int i = 0; i < 4; i++) {
                    mma_f16(accg[i][jn], a[i], bg[jn]);
                    mma_f16(accu[i][jn], a[i], bu[jn]);
                }
        }
    }

    // epilogue: silu(g)*u -> fp16
    #pragma unroll
    for (int i = 0; i < 4; i++) {
        #pragma unroll
        for (int half_ = 0; half_ < 2; half_++) {
            int r = m0 + i*16 + half_*8 + tg;
            int lrow = row0 + r;
            if (lrow < M) {
                __half* hrow = Hout + (size_t)lrow * NI + col0 + n0;
                #pragma unroll
                for (int jn = 0; jn < 4; jn++) {
                    float g0 = accg[i][jn][half_*2+0], g1 = accg[i][jn][half_*2+1];
                    float u0 = accu[i][jn][half_*2+0], u1 = accu[i][jn][half_*2+1];
                    float h0 = g0 / (1.f + expf(-g0)) * u0;
                    float h1 = g1 / (1.f + expf(-g1)) * u1;
                    __half2 hv = __floats2half2_rn(h0, h1);
                    *reinterpret_cast<__half2*>(hrow + jn*8 + 2*ti) = hv;
                }
            }
        }
    }
}

// ---------------- down GEMM (fp16 mma + ldmatrix) ------------------------------
// Block 128(M) x 256(N). 8 warps, warp tile 64x64.
// EXPERT=true: scatter rows to g_down. EXPERT=false (runs LAST): fused combine,
// writes out = shared + w0*d0 + w1*d1 directly.
template<bool EXPERT>
__global__ __launch_bounds__(256, 1)
void down_mma(const __half* __restrict__ WdT,    // [*, NH, NI] k-contig
              float* __restrict__ outp) {
    extern __shared__ __align__(16) char dsm[];
    const int e    = EXPERT ? blockIdx.z : 0;
    const int M    = EXPERT ? g_cnt[e] : NT;
    const int row0 = blockIdx.y * 128;
    if (row0 >= M) return;
    const int col0 = blockIdx.x * 256;

    const __half* A  = EXPERT ? (g_hbuf + (size_t)e * NT * NI) : g_shh;
    const __half* wd = WdT + (EXPERT ? (size_t)e * NH * NI : (size_t)0);

    const int tid = threadIdx.x, wid = tid >> 5, lane = tid & 31;
    const uint32_t sbase = smem_u32(dsm);

    const __half* s0; const __half* s1;
    uint32_t d0, d1;
    if (tid < 128) {
        int r = tid;
        int ar = row0 + r; if (ar >= M) ar = M - 1;
        s0 = s1 = A + (size_t)ar * NI;
        d0 = d1 = (uint32_t)r * PADH;
    } else {
        int u = tid - 128;
        s0 = wd + (size_t)(col0 + u)       * NI;
        s1 = wd + (size_t)(col0 + u + 128) * NI;
        d0 = DN_B_OFF + (uint32_t)u * PADH;
        d1 = DN_B_OFF + (uint32_t)(u + 128) * PADH;
    }
    const bool tworow = (tid >= 128);

    float acc[4][8][4];
    #pragma unroll
    for (int i = 0; i < 4; i++)
        #pragma unroll
        for (int j = 0; j < 8; j++)
            #pragma unroll
            for (int q = 0; q < 4; q++) acc[i][j][q] = 0.f;

    const int m0 = (wid & 1) * 64, n0 = (wid >> 1) * 64;
    const int tg = lane >> 2, ti = lane & 3;

    const int q8 = lane >> 3, l7 = lane & 7;
    const uint32_t aoff = (uint32_t)((m0 + (q8 & 1)*8 + l7) * PADH + (q8 >> 1)*8) * 2;
    const uint32_t boff = (uint32_t)(DN_B_OFF + (n0 + (q8 >> 1)*8 + l7) * PADH + (q8 & 1)*8) * 2;

    int koff = 0;
    #pragma unroll
    for (int s = 0; s < NSTAGE - 1; s++) {
        uint32_t base = sbase + (uint32_t)(s * DN_STAGE) * 2;
        #pragma unroll
        for (int c = 0; c < 8; c++) cpa16(base + d0*2 + c*16, s0 + koff + c*8);
        if (tworow) {
            #pragma unroll
            for (int c = 0; c < 8; c++) cpa16(base + d1*2 + c*16, s1 + koff + c*8);
        }
        cp_commit();
        koff += KC;
    }

    const int KST = NI / KC;   // 22
    for (int j = 0; j < KST; j++) {
        if      (j < KST - 2) asm volatile("cp.async.wait_group 2;" ::: "memory");
        else if (j < KST - 1) asm volatile("cp.async.wait_group 1;" ::: "memory");
        else                  asm volatile("cp.async.wait_group 0;" ::: "memory");
        __syncthreads();
        if (j + NSTAGE - 1 < KST) {
            int s = (j + NSTAGE - 1) % NSTAGE;
            uint32_t base = sbase + (uint32_t)(s * DN_STAGE) * 2;
            #pragma unroll
            for (int c = 0; c < 8; c++) cpa16(base + d0*2 + c*16, s0 + koff + c*8);
            if (tworow) {
                #pragma unroll
                for (int c = 0; c < 8; c++) cpa16(base + d1*2 + c*16, s1 + koff + c*8);
            }
            cp_commit();
            koff += KC;
        }
        const uint32_t stg = sbase + (uint32_t)((j % NSTAGE) * DN_STAGE) * 2;
        #pragma unroll
        for (int kk = 0; kk < 4; kk++) {
            const uint32_t kb = (uint32_t)(kk * 16) * 2;
            uint32_t a[4][4];
            #pragma unroll
            for (int i = 0; i < 4; i++)
                ldsm4(stg + aoff + (uint32_t)(i*16*PADH)*2 + kb,
                      a[i][0], a[i][1], a[i][2], a[i][3]);
            uint32_t b[8][2];
            #pragma unroll
            for (int jp = 0; jp < 4; jp++)
                ldsm4(stg + boff + (uint32_t)(jp*16*PADH)*2 + kb,
                      b[2*jp][0], b[2*jp][1], b[2*jp+1][0], b[2*jp+1][1]);
            #pragma unroll
            for (int jn = 0; jn < 8; jn++)
                #pragma unroll
                for (int i = 0; i < 4; i++)
                    mma_f16(acc[i][jn], a[i], b[jn]);
        }
    }

    #pragma unroll
    for (int i = 0; i < 4; i++) {
        #pragma unroll
        for (int half_ = 0; half_ < 2; half_++) {
            int r = m0 + i*16 + half_*8 + tg;
            int lrow = row0 + r;
            if (lrow < M) {
                if (EXPERT) {
                    float* crow = g_down + (size_t)g_pidlist[e*NT + lrow] * NH + col0 + n0;
                    #pragma unroll
                    for (int jn = 0; jn < 8; jn++) {
                        float2 v;
                        v.x = acc[i][jn][half_*2+0];
                        v.y = acc[i][jn][half_*2+1];
                        *reinterpret_cast<float2*>(crow + jn*8 + 2*ti) = v;
                    }
                } else {
                    // fused combine: out = shared + w0*d0 + w1*d1
                    float w0 = g_w[2*lrow], w1 = g_w[2*lrow+1];
                    const float* e0 = g_down + (size_t)(2*lrow)   * NH + col0 + n0;
                    const float* e1 = g_down + (size_t)(2*lrow+1) * NH + col0 + n0;
                    float* crow = outp + (size_t)lrow * NH + col0 + n0;
                    #pragma unroll
                    for (int jn = 0; jn < 8; jn++) {
                        int off = jn*8 + 2*ti;
                        float2 a2 = *reinterpret_cast<const float2*>(e0 + off);
                        float2 b2 = *reinterpret_cast<const float2*>(e1 + off);
                        float2 v;
                        v.x = fmaf(w1, b2.x, fmaf(w0, a2.x, acc[i][jn][half_*2+0]));
                        v.y = fmaf(w1, b2.y, fmaf(w0, a2.y, acc[i][jn][half_*2+1]));
                        *reinterpret_cast<float2*>(crow + off) = v;
                    }
                }
            }
        }
    }
}

// ---------------- launch ----------------------------------------------------------
extern "C" void kernel_launch(void* const* d_in, const int* in_sizes, int n_in,
                              void* d_out, int out_size) {
    const float* x  = (const float*)d_in[0];
    const float* gw = (const float*)d_in[1];
    const float* eg = (const float*)d_in[2];
    const float* eu = (const float*)d_in[3];
    const float* ed = (const float*)d_in[4];
    const float* sg = (const float*)d_in[5];
    const float* su = (const float*)d_in[6];
    const float* sd = (const float*)d_in[7];
    float* out = (float*)d_out;

    static bool attr_done = false;
    if (!attr_done) {
        cudaFuncSetAttribute(gateup_mma<false>, cudaFuncAttributeMaxDynamicSharedMemorySize, GU_SMEM_BYTES);
        cudaFuncSetAttribute(gateup_mma<true>,  cudaFuncAttributeMaxDynamicSharedMemorySize, GU_SMEM_BYTES);
        cudaFuncSetAttribute(down_mma<false>,   cudaFuncAttributeMaxDynamicSharedMemorySize, DN_SMEM_BYTES);
        cudaFuncSetAttribute(down_mma<true>,    cudaFuncAttributeMaxDynamicSharedMemorySize, DN_SMEM_BYTES);
        attr_done = true;
    }

    __half *p_xh, *p_egT, *p_euT, *p_edT, *p_sgT, *p_suT, *p_sdT;
    cudaGetSymbolAddress((void**)&p_xh,  g_xh);
    cudaGetSymbolAddress((void**)&p_egT, g_egT);
    cudaGetSymbolAddress((void**)&p_euT, g_euT);
    cudaGetSymbolAddress((void**)&p_edT, g_edT);
    cudaGetSymbolAddress((void**)&p_sgT, g_sgT);
    cudaGetSymbolAddress((void**)&p_suT, g_suT);
    cudaGetSymbolAddress((void**)&p_sdT, g_sdT);

    zero_cnt_kernel<<<1, 32>>>();
    router_kernel<<<NT/4, 128>>>(x, gw);

    // fp16 conversion (+ transpose for weights: [K][N] -> [N][K])
    cvt_kernel<<<512, 256>>>(x, p_xh, NT*NH/4);
    dim3 tb(32, 8);
    transcvt_kernel<<<dim3(NI/32, NH/64, NE), tb>>>(eg, p_egT, NH, NI);
    transcvt_kernel<<<dim3(NI/32, NH/64, NE), tb>>>(eu, p_euT, NH, NI);
    transcvt_kernel<<<dim3(NH/32, NI/64, NE), tb>>>(ed, p_edT, NI, NH);
    transcvt_kernel<<<dim3(NI/32, NH/64, 1),  tb>>>(sg, p_sgT, NH, NI);
    transcvt_kernel<<<dim3(NI/32, NH/64, 1),  tb>>>(su, p_suT, NH, NI);
    transcvt_kernel<<<dim3(NH/32, NI/64, 1),  tb>>>(sd, p_sdT, NI, NH);

    // gate+up SwiGLU
    gateup_mma<false><<<dim3(NI/128, NT/128, 1),  256, GU_SMEM_BYTES>>>(p_sgT, p_suT);
    gateup_mma<true> <<<dim3(NI/128, NT/128, NE), 256, GU_SMEM_BYTES>>>(p_egT, p_euT);

    // down projection: experts first (fill g_down), then shared (fused combine)
    down_mma<true> <<<dim3(NH/256, NT/128, NE), 256, DN_SMEM_BYTES>>>(p_edT, out);
    down_mma<false><<<dim3(NH/256, NT/128, 1),  256, DN_SMEM_BYTES>>>(p_sdT, out);
}

// round 11
// speedup vs baseline: 1.0001x; 1.0001x over previous
#include <cuda_runtime.h>
#include <cuda_fp16.h>
#include <math.h>
#include <stdint.h>

// Problem dims (fixed)
#define NT 8192   // tokens
#define NH 1024   // hidden
#define NE 8      // experts
#define NI 1408   // intermediate

#define KC 64     // K halfs per pipeline stage
#define NSTAGE 3
#define PADH 72   // halfs per smem row (144B: ldmatrix row banks conflict-free)

// gateup stage (halfs): A[128][72] + Bg[128][72] + Bu[128][72]
#define GU_BG_OFF (128 * PADH)
#define GU_BU_OFF (256 * PADH)
#define GU_STAGE  (384 * PADH)
#define GU_SMEM_BYTES (NSTAGE * GU_STAGE * 2)        // 165888

// down stage (halfs): A[128][72] + B[256][72]
#define DN_B_OFF  (128 * PADH)
#define DN_STAGE  (384 * PADH)
#define DN_SMEM_BYTES (NSTAGE * DN_STAGE * 2)        // 165888

// ---------------- scratch (device globals) ----------------------------------
__device__ __half g_xh [(size_t)NT*NH];
__device__ __half g_egT[(size_t)NE*NI*NH];       // fp16 weights, [N][K]
__device__ __half g_euT[(size_t)NE*NI*NH];
__device__ __half g_edT[(size_t)NE*NH*NI];
__device__ __half g_sgT[(size_t)NI*NH];
__device__ __half g_suT[(size_t)NI*NH];
__device__ __half g_sdT[(size_t)NH*NI];
__device__ __half g_hbuf[(size_t)NE*NT*NI];
__device__ __half g_shh [(size_t)NT*NI];
__device__ float  g_down[(size_t)2*NT*NH];
__device__ int    g_rowlist[NE*NT];
__device__ int    g_pidlist[NE*NT];
__device__ int    g_cnt[NE];
__device__ float  g_w[NT*2];

// ---------------- helpers ----------------------------------------------------
__device__ __forceinline__ uint32_t smem_u32(const void* p) {
    uint32_t a;
    asm("{ .reg .u64 t; cvta.to.shared.u64 t, %1; cvt.u32.u64 %0, t; }" : "=r"(a) : "l"(p));
    return a;
}
__device__ __forceinline__ void cpa16(uint32_t dst, const void* src) {
    asm volatile("cp.async.cg.shared.global [%0], [%1], 16;" :: "r"(dst), "l"(src) : "memory");
}
__device__ __forceinline__ void cp_commit() {
    asm volatile("cp.async.commit_group;" ::: "memory");
}
__device__ __forceinline__ void mma_f16(float* c, const uint32_t* a, const uint32_t* b) {
    asm volatile(
        "mma.sync.aligned.m16n8k16.row.col.f32.f16.f16.f32 "
        "{%0,%1,%2,%3}, {%4,%5,%6,%7}, {%8,%9}, {%0,%1,%2,%3};"
        : "+f"(c[0]), "+f"(c[1]), "+f"(c[2]), "+f"(c[3])
        : "r"(a[0]), "r"(a[1]), "r"(a[2]), "r"(a[3]), "r"(b[0]), "r"(b[1]));
}
__device__ __forceinline__ void ldsm4(uint32_t addr, uint32_t& r0, uint32_t& r1,
                                      uint32_t& r2, uint32_t& r3) {
    asm volatile("ldmatrix.sync.aligned.m8n8.x4.shared.b16 {%0,%1,%2,%3}, [%4];"
                 : "=r"(r0), "=r"(r1), "=r"(r2), "=r"(r3) : "r"(addr));
}

// ---------------- small kernels ----------------------------------------------
__global__ void zero_cnt_kernel() {
    if (threadIdx.x < NE) g_cnt[threadIdx.x] = 0;
}

__global__ void cvt_kernel(const float* __restrict__ in, __half* __restrict__ out, int n4) {
    int i = blockIdx.x * blockDim.x + threadIdx.x;
    int stride = gridDim.x * blockDim.x;
    for (; i < n4; i += stride) {
        float4 v = reinterpret_cast<const float4*>(in)[i];
        __half2 lo = __floats2half2_rn(v.x, v.y);
        __half2 hi = __floats2half2_rn(v.z, v.w);
        uint2 pk = make_uint2(*reinterpret_cast<uint32_t*>(&lo),
                              *reinterpret_cast<uint32_t*>(&hi));
        reinterpret_cast<uint2*>(out)[i] = pk;
    }
}

// [R][C] f32 -> [C][R] f16; 64(R) x 32(C) tiles, half2 stores
__global__ void transcvt_kernel(const float* __restrict__ in, __half* __restrict__ out,
                                int R, int C) {
    __shared__ float tile[32][65];   // [c][r]
    size_t boff = (size_t)blockIdx.z * R * C;
    const float* ib = in + boff;
    __half* ob = out + boff;
    int c0 = blockIdx.x * 32, r0 = blockIdx.y * 64;
    int tx = threadIdx.x, ty = threadIdx.y;
    #pragma unroll
    for (int i = 0; i < 8; i++) {
        int r = ty + 8*i;
        tile[tx][r] = ib[(size_t)(r0 + r) * C + c0 + tx];
    }
    __syncthreads();
    #pragma unroll
    for (int ic = 0; ic < 4; ic++) {
        int c = ty + 8*ic;
        __half2 v = __floats2half2_rn(tile[c][2*tx], tile[c][2*tx+1]);
        *reinterpret_cast<__half2*>(ob + (size_t)(c0 + c) * R + r0 + 2*tx) = v;
    }
}

// ---------------- router ------------------------------------------------------
__global__ void router_kernel(const float* __restrict__ x,
                              const float* __restrict__ gw) {
    int gtid = blockIdx.x * blockDim.x + threadIdx.x;
    int t    = gtid >> 5;
    int lane = gtid & 31;
    if (t >= NT) return;
    const float* xr = x + (size_t)t * NH;

    float acc[8] = {0.f,0.f,0.f,0.f,0.f,0.f,0.f,0.f};
    for (int h = lane; h < NH; h += 32) {
        float xv = __ldg(xr + h);
        const float4* g4 = reinterpret_cast<const float4*>(gw + (size_t)h * 8);
        float4 a = __ldg(g4 + 0);
        float4 b = __ldg(g4 + 1);
        acc[0] = fmaf(xv, a.x, acc[0]); acc[1] = fmaf(xv, a.y, acc[1]);
        acc[2] = fmaf(xv, a.z, acc[2]); acc[3] = fmaf(xv, a.w, acc[3]);
        acc[4] = fmaf(xv, b.x, acc[4]); acc[5] = fmaf(xv, b.y, acc[5]);
        acc[6] = fmaf(xv, b.z, acc[6]); acc[7] = fmaf(xv, b.w, acc[7]);
    }
    #pragma unroll
    for (int e = 0; e < 8; e++)
        #pragma unroll
        for (int off = 16; off > 0; off >>= 1)
            acc[e] += __shfl_xor_sync(0xffffffffu, acc[e], off);
    if (lane == 0) {
        float m = acc[0];
        #pragma unroll
        for (int e = 1; e < 8; e++) m = fmaxf(m, acc[e]);
        float p[8], s = 0.f;
        #pragma unroll
        for (int e = 0; e < 8; e++) { p[e] = expf(acc[e] - m); s += p[e]; }
        float inv = 1.f / s;
        #pragma unroll
        for (int e = 0; e < 8; e++) p[e] *= inv;
        int i0 = 0; float v0 = p[0];
        #pragma unroll
        for (int e = 1; e < 8; e++) if (p[e] > v0) { v0 = p[e]; i0 = e; }
        int i1 = -1; float v1 = -1.f;
        #pragma unroll
        for (int e = 0; e < 8; e++) if (e != i0 && p[e] > v1) { v1 = p[e]; i1 = e; }
        float denom = v0 + v1 + 1e-6f;
        g_w[2*t]   = v0 / denom;
        g_w[2*t+1] = v1 / denom;
        int r0 = atomicAdd(&g_cnt[i0], 1);
        g_rowlist[i0*NT + r0] = t; g_pidlist[i0*NT + r0] = 2*t;
        int r1 = atomicAdd(&g_cnt[i1], 1);
        g_rowlist[i1*NT + r1] = t; g_pidlist[i1*NT + r1] = 2*t + 1;
    }
}

// ---------------- gate+up SwiGLU GEMM (fp16 mma + ldmatrix) --------------------
// Block 128(M) x 128(N per matrix). 8 warps, warp tile 64x32 per matrix.
template<bool EXPERT>
__global__ __launch_bounds__(256, 1)
void gateup_mma(const __half* __restrict__ WgT,   // [*, NI, NH] k-contig
                const __half* __restrict__ WuT) {
    extern __shared__ __align__(16) char dsm[];
    const int e    = EXPERT ? blockIdx.z : 0;
    const int M    = EXPERT ? g_cnt[e] : NT;
    const int row0 = blockIdx.y * 128;
    if (row0 >= M) return;
    const int col0 = blockIdx.x * 128;

    const __half* wg = WgT + (EXPERT ? (size_t)e * NI * NH : (size_t)0);
    const __half* wu = WuT + (EXPERT ? (size_t)e * NI * NH : (size_t)0);
    __half* Hout = EXPERT ? (g_hbuf + (size_t)e * NT * NI) : g_shh;

    const int tid = threadIdx.x, wid = tid >> 5, lane = tid & 31;
    const uint32_t sbase = smem_u32(dsm);

    // copy roles
    const __half* s0; const __half* s1;
    uint32_t d0, d1;
    if (tid < 128) {
        int r = tid;
        int li = row0 + r; if (li >= M) li = M - 1;
        int gr = EXPERT ? g_rowlist[e*NT + li] : li;
        s0 = s1 = g_xh + (size_t)gr * NH;
        d0 = d1 = (uint32_t)r * PADH;
    } else if (tid < 192) {
        int u = tid - 128;
        s0 = wg + (size_t)(col0 + u)      * NH;
        s1 = wg + (size_t)(col0 + u + 64) * NH;
        d0 = GU_BG_OFF + (uint32_t)u * PADH;
        d1 = GU_BG_OFF + (uint32_t)(u + 64) * PADH;
    } else {
        int u = tid - 192;
        s0 = wu + (size_t)(col0 + u)      * NH;
        s1 = wu + (size_t)(col0 + u + 64) * NH;
        d0 = GU_BU_OFF + (uint32_t)u * PADH;
        d1 = GU_BU_OFF + (uint32_t)(u + 64) * PADH;
    }
    const bool tworow = (tid >= 128);

    float accg[4][4][4], accu[4][4][4];
    #pragma unroll
    for (int i = 0; i < 4; i++)
        #pragma unroll
        for (int j = 0; j < 4; j++)
            #pragma unroll
            for (int q = 0; q < 4; q++) { accg[i][j][q] = 0.f; accu[i][j][q] = 0.f; }

    const int m0 = (wid & 1) * 64, n0 = (wid >> 1) * 32;
    const int tg = lane >> 2, ti = lane & 3;

    const int q8 = lane >> 3, l7 = lane & 7;
    const uint32_t aoff  = (uint32_t)((m0 + (q8 & 1)*8 + l7) * PADH + (q8 >> 1)*8) * 2;
    const uint32_t bgoff = (uint32_t)(GU_BG_OFF + (n0 + (q8 >> 1)*8 + l7) * PADH + (q8 & 1)*8) * 2;
    const uint32_t buoff = (uint32_t)(GU_BU_OFF + (n0 + (q8 >> 1)*8 + l7) * PADH + (q8 & 1)*8) * 2;

    int koff = 0;
    #pragma unroll
    for (int s = 0; s < NSTAGE - 1; s++) {
        uint32_t base = sbase + (uint32_t)(s * GU_STAGE) * 2;
        #pragma unroll
        for (int c = 0; c < 8; c++) cpa16(base + d0*2 + c*16, s0 + koff + c*8);
        if (tworow) {
            #pragma unroll
            for (int c = 0; c < 8; c++) cpa16(base + d1*2 + c*16, s1 + koff + c*8);
        }
        cp_commit();
        koff += KC;
    }

    const int KST = NH / KC;   // 16
    for (int j = 0; j < KST; j++) {
        if (j < KST - 1) asm volatile("cp.async.wait_group 1;" ::: "memory");
        else             asm volatile("cp.async.wait_group 0;" ::: "memory");
        __syncthreads();
        if (j + NSTAGE - 1 < KST) {
            int s = (j + NSTAGE - 1) % NSTAGE;
            uint32_t base = sbase + (uint32_t)(s * GU_STAGE) * 2;
            #pragma unroll
            for (int c = 0; c < 8; c++) cpa16(base + d0*2 + c*16, s0 + koff + c*8);
            if (tworow) {
                #pragma unroll
                for (int c = 0; c < 8; c++) cpa16(base + d1*2 + c*16, s1 + koff + c*8);
            }
            cp_commit();
            koff += KC;
        }
        const uint32_t stg = sbase + (uint32_t)((j % NSTAGE) * GU_STAGE) * 2;
        #pragma unroll
        for (int kk = 0; kk < 4; kk++) {
            const uint32_t kb = (uint32_t)(kk * 16) * 2;
            uint32_t a[4][4];
            #pragma unroll
            for (int i = 0; i < 4; i++)
                ldsm4(stg + aoff + (uint32_t)(i*16*PADH)*2 + kb,
                      a[i][0], a[i][1], a[i][2], a[i][3]);
            uint32_t bg[4][2], bu[4][2];
            #pragma unroll
            for (int jp = 0; jp < 2; jp++) {
                ldsm4(stg + bgoff + (uint32_t)(jp*16*PADH)*2 + kb,
                      bg[2*jp][0], bg[2*jp][1], bg[2*jp+1][0], bg[2*jp+1][1]);
                ldsm4(stg + buoff + (uint32_t)(jp*16*PADH)*2 + kb,
                      bu[2*jp][0], bu[2*jp][1], bu[2*jp+1][0], bu[2*jp+1][1]);
            }
            #pragma unroll
            for (int jn = 0; jn < 4; jn++)
                #pragma unroll
                for (int i = 0; i < 4; i++) {
                    mma_f16(accg[i][jn], a[i], bg[jn]);
                    mma_f16(accu[i][jn], a[i], bu[jn]);
                }
        }
    }

    // epilogue: silu(g)*u -> fp16
    #pragma unroll
    for (int i = 0; i < 4; i++) {
        #pragma unroll
        for (int half_ = 0; half_ < 2; half_++) {
            int r = m0 + i*16 + half_*8 + tg;
            int lrow = row0 + r;
            if (lrow < M) {
                __half* hrow = Hout + (size_t)lrow * NI + col0 + n0;
                #pragma unroll
                for (int jn = 0; jn < 4; jn++) {
                    float g0 = accg[i][jn][half_*2+0], g1 = accg[i][jn][half_*2+1];
                    float u0 = accu[i][jn][half_*2+0], u1 = accu[i][jn][half_*2+1];
                    float h0 = g0 / (1.f + expf(-g0)) * u0;
                    float h1 = g1 / (1.f + expf(-g1)) * u1;
                    __half2 hv = __floats2half2_rn(h0, h1);
                    *reinterpret_cast<__half2*>(hrow + jn*8 + 2*ti) = hv;
                }
            }
        }
    }
}

// ---------------- down GEMM (fp16 mma + ldmatrix) ------------------------------
// Block 128(M) x 256(N). 8 warps, warp tile 64x64.
// EXPERT=true: scatter rows to g_down. EXPERT=false (runs LAST): fused combine.
template<bool EXPERT>
__global__ __launch_bounds__(256, 1)
void down_mma(const __half* __restrict__ WdT,    // [*, NH, NI] k-contig
              float* __restrict__ outp) {
    extern __shared__ __align__(16) char dsm[];
    const int e    = EXPERT ? blockIdx.z : 0;
    const int M    = EXPERT ? g_cnt[e] : NT;
    const int row0 = blockIdx.y * 128;
    if (row0 >= M) return;
    const int col0 = blockIdx.x * 256;

    const __half* A  = EXPERT ? (g_hbuf + (size_t)e * NT * NI) : g_shh;
    const __half* wd = WdT + (EXPERT ? (size_t)e * NH * NI : (size_t)0);

    const int tid = threadIdx.x, wid = tid >> 5, lane = tid & 31;
    const uint32_t sbase = smem_u32(dsm);

    const __half* s0; const __half* s1;
    uint32_t d0, d1;
    if (tid < 128) {
        int r = tid;
        int ar = row0 + r; if (ar >= M) ar = M - 1;
        s0 = s1 = A + (size_t)ar * NI;
        d0 = d1 = (uint32_t)r * PADH;
    } else {
        int u = tid - 128;
        s0 = wd + (size_t)(col0 + u)       * NI;
        s1 = wd + (size_t)(col0 + u + 128) * NI;
        d0 = DN_B_OFF + (uint32_t)u * PADH;
        d1 = DN_B_OFF + (uint32_t)(u + 128) * PADH;
    }
    const bool tworow = (tid >= 128);

    float acc[4][8][4];
    #pragma unroll
    for (int i = 0; i < 4; i++)
        #pragma unroll
        for (int j = 0; j < 8; j++)
            #pragma unroll
            for (int q = 0; q < 4; q++) acc[i][j][q] = 0.f;

    const int m0 = (wid & 1) * 64, n0 = (wid >> 1) * 64;
    const int tg = lane >> 2, ti = lane & 3;

    const int q8 = lane >> 3, l7 = lane & 7;
    const uint32_t aoff = (uint32_t)((m0 + (q8 & 1)*8 + l7) * PADH + (q8 >> 1)*8) * 2;
    const uint32_t boff = (uint32_t)(DN_B_OFF + (n0 + (q8 >> 1)*8 + l7) * PADH + (q8 & 1)*8) * 2;

    int koff = 0;
    #pragma unroll
    for (int s = 0; s < NSTAGE - 1; s++) {
        uint32_t base = sbase + (uint32_t)(s * DN_STAGE) * 2;
        #pragma unroll
        for (int c = 0; c < 8; c++) cpa16(base + d0*2 + c*16, s0 + koff + c*8);
        if (tworow) {
            #pragma unroll
            for (int c = 0; c < 8; c++) cpa16(base + d1*2 + c*16, s1 + koff + c*8);
        }
        cp_commit();
        koff += KC;
    }

    const int KST = NI / KC;   // 22
    for (int j = 0; j < KST; j++) {
        if (j < KST - 1) asm volatile("cp.async.wait_group 1;" ::: "memory");
        else             asm volatile("cp.async.wait_group 0;" ::: "memory");
        __syncthreads();
        if (j + NSTAGE - 1 < KST) {
            int s = (j + NSTAGE - 1) % NSTAGE;
            uint32_t base = sbase + (uint32_t)(s * DN_STAGE) * 2;
            #pragma unroll
            for (int c = 0; c < 8; c++) cpa16(base + d0*2 + c*16, s0 + koff + c*8);
            if (tworow) {
                #pragma unroll
                for (int c = 0; c < 8; c++) cpa16(base + d1*2 + c*16, s1 + koff + c*8);
            }
            cp_commit();
            koff += KC;
        }
        const uint32_t stg = sbase + (uint32_t)((j % NSTAGE) * DN_STAGE) * 2;
        #pragma unroll
        for (int kk = 0; kk < 4; kk++) {
            const uint32_t kb = (uint32_t)(kk * 16) * 2;
            uint32_t a[4][4];
            #pragma unroll
            for (int i = 0; i < 4; i++)
                ldsm4(stg + aoff + (uint32_t)(i*16*PADH)*2 + kb,
                      a[i][0], a[i][1], a[i][2], a[i][3]);
            uint32_t b[8][2];
            #pragma unroll
            for (int jp = 0; jp < 4; jp++)
                ldsm4(stg + boff + (uint32_t)(jp*16*PADH)*2 + kb,
                      b[2*jp][0], b[2*jp][1], b[2*jp+1][0], b[2*jp+1][1]);
            #pragma unroll
            for (int jn = 0; jn < 8; jn++)
                #pragma unroll
                for (int i = 0; i < 4; i++)
                    mma_f16(acc[i][jn], a[i], b[jn]);
        }
    }

    #pragma unroll
    for (int i = 0; i < 4; i++) {
        #pragma unroll
        for (int half_ = 0; half_ < 2; half_++) {
            int r = m0 + i*16 + half_*8 + tg;
            int lrow = row0 + r;
            if (lrow < M) {
                if (EXPERT) {
                    float* crow = g_down + (size_t)g_pidlist[e*NT + lrow] * NH + col0 + n0;
                    #pragma unroll
                    for (int jn = 0; jn < 8; jn++) {
                        float2 v;
                        v.x = acc[i][jn][half_*2+0];
                        v.y = acc[i][jn][half_*2+1];
                        *reinterpret_cast<float2*>(crow + jn*8 + 2*ti) = v;
                    }
                } else {
                    // fused combine: out = shared + w0*d0 + w1*d1
                    float w0 = g_w[2*lrow], w1 = g_w[2*lrow+1];
                    const float* e0 = g_down + (size_t)(2*lrow)   * NH + col0 + n0;
                    const float* e1 = g_down + (size_t)(2*lrow+1) * NH + col0 + n0;
                    float* crow = outp + (size_t)lrow * NH + col0 + n0;
                    #pragma unroll
                    for (int jn = 0; jn < 8; jn++) {
                        int off = jn*8 + 2*ti;
                        float2 a2 = *reinterpret_cast<const float2*>(e0 + off);
                        float2 b2 = *reinterpret_cast<const float2*>(e1 + off);
                        float2 v;
                        v.x = fmaf(w1, b2.x, fmaf(w0, a2.x, acc[i][jn][half_*2+0]));
                        v.y = fmaf(w1, b2.y, fmaf(w0, a2.y, acc[i][jn][half_*2+1]));
                        *reinterpret_cast<float2*>(crow + off) = v;
                    }
                }
            }
        }
    }
}

// ---------------- launch ----------------------------------------------------------
extern "C" void kernel_launch(void* const* d_in, const int* in_sizes, int n_in,
                              void* d_out, int out_size) {
    const float* x  = (const float*)d_in[0];
    const float* gw = (const float*)d_in[1];
    const float* eg = (const float*)d_in[2];
    const float* eu = (const float*)d_in[3];
    const float* ed = (const float*)d_in[4];
    const float* sg = (const float*)d_in[5];
    const float* su = (const float*)d_in[6];
    const float* sd = (const float*)d_in[7];
    float* out = (float*)d_out;

    static bool attr_done = false;
    if (!attr_done) {
        cudaFuncSetAttribute(gateup_mma<false>, cudaFuncAttributeMaxDynamicSharedMemorySize, GU_SMEM_BYTES);
        cudaFuncSetAttribute(gateup_mma<true>,  cudaFuncAttributeMaxDynamicSharedMemorySize, GU_SMEM_BYTES);
        cudaFuncSetAttribute(down_mma<false>,   cudaFuncAttributeMaxDynamicSharedMemorySize, DN_SMEM_BYTES);
        cudaFuncSetAttribute(down_mma<true>,    cudaFuncAttributeMaxDynamicSharedMemorySize, DN_SMEM_BYTES);
        attr_done = true;
    }

    __half *p_xh, *p_egT, *p_euT, *p_edT, *p_sgT, *p_suT, *p_sdT;
    cudaGetSymbolAddress((void**)&p_xh,  g_xh);
    cudaGetSymbolAddress((void**)&p_egT, g_egT);
    cudaGetSymbolAddress((void**)&p_euT, g_euT);
    cudaGetSymbolAddress((void**)&p_edT, g_edT);
    cudaGetSymbolAddress((void**)&p_sgT, g_sgT);
    cudaGetSymbolAddress((void**)&p_suT, g_suT);
    cudaGetSymbolAddress((void**)&p_sdT, g_sdT);

    zero_cnt_kernel<<<1, 32>>>();
    router_kernel<<<NT/4, 128>>>(x, gw);

    // fp16 conversion (+ transpose for weights: [K][N] -> [N][K])
    cvt_kernel<<<512, 256>>>(x, p_xh, NT*NH/4);
    dim3 tb(32, 8);
    transcvt_kernel<<<dim3(NI/32, NH/64, NE), tb>>>(eg, p_egT, NH, NI);
    transcvt_kernel<<<dim3(NI/32, NH/64, NE), tb>>>(eu, p_euT, NH, NI);
    transcvt_kernel<<<dim3(NH/32, NI/64, NE), tb>>>(ed, p_edT, NI, NH);
    transcvt_kernel<<<dim3(NI/32, NH/64, 1),  tb>>>(sg, p_sgT, NH, NI);
    transcvt_kernel<<<dim3(NI/32, NH/64, 1),  tb>>>(su, p_suT, NH, NI);
    transcvt_kernel<<<dim3(NH/32, NI/64, 1),  tb>>>(sd, p_sdT, NI, NH);

    // gate+up SwiGLU
    gateup_mma<false><<<dim3(NI/128, NT/128, 1),  256, GU_SMEM_BYTES>>>(p_sgT, p_suT);
    gateup_mma<true> <<<dim3(NI/128, NT/128, NE), 256, GU_SMEM_BYTES>>>(p_egT, p_euT);

    // down projection: experts first (fill g_down), then shared (fused combine)
    down_mma<true> <<<dim3(NH/256, NT/128, NE), 256, DN_SMEM_BYTES>>>(p_edT, out);
    down_mma<false><<<dim3(NH/256, NT/128, 1),  256, DN_SMEM_BYTES>>>(p_sdT, out);
}

// round 12
// speedup vs baseline: 1.0428x; 1.0427x over previous
#include <cuda_runtime.h>
#include <cuda_fp16.h>
#include <math.h>
#include <stdint.h>

// Problem dims (fixed)
#define NT 8192   // tokens
#define NH 1024   // hidden
#define NE 8      // experts
#define NI 1408   // intermediate

#define KC 64     // K halfs per pipeline stage
#define NSTAGE 3
#define PADH 72   // halfs per smem row (144B: ldmatrix row banks conflict-free)

// gateup stage (halfs): A[128][72] + Bg[128][72] + Bu[128][72]
#define GU_BG_OFF (128 * PADH)
#define GU_BU_OFF (256 * PADH)
#define GU_STAGE  (384 * PADH)
#define GU_SMEM_BYTES (NSTAGE * GU_STAGE * 2)        // 165888

// down stage (halfs): A[128][72] + B[256][72]
#define DN_B_OFF  (128 * PADH)
#define DN_STAGE  (384 * PADH)
#define DN_SMEM_BYTES (NSTAGE * DN_STAGE * 2)        // 165888

// ---------------- scratch (device globals) ----------------------------------
__device__ __half g_xh [(size_t)NT*NH];
__device__ __half g_egT[(size_t)NE*NI*NH];       // fp16 weights, [N][K]
__device__ __half g_euT[(size_t)NE*NI*NH];
__device__ __half g_edT[(size_t)NE*NH*NI];
__device__ __half g_sgT[(size_t)NI*NH];
__device__ __half g_suT[(size_t)NI*NH];
__device__ __half g_sdT[(size_t)NH*NI];
__device__ __half g_hbuf[(size_t)NE*NT*NI];
__device__ __half g_shh [(size_t)NT*NI];
__device__ float  g_down[(size_t)2*NT*NH];
__device__ int    g_rowlist[NE*NT];
__device__ int    g_pidlist[NE*NT];
__device__ int    g_cnt[NE];                     // static zero-init; re-zeroed at END
__device__ float  g_w[NT*2];

// ---------------- helpers ----------------------------------------------------
__device__ __forceinline__ uint32_t smem_u32(const void* p) {
    uint32_t a;
    asm("{ .reg .u64 t; cvta.to.shared.u64 t, %1; cvt.u32.u64 %0, t; }" : "=r"(a) : "l"(p));
    return a;
}
__device__ __forceinline__ void cpa16(uint32_t dst, const void* src) {
    asm volatile("cp.async.cg.shared.global [%0], [%1], 16;" :: "r"(dst), "l"(src) : "memory");
}
__device__ __forceinline__ void cp_commit() {
    asm volatile("cp.async.commit_group;" ::: "memory");
}
__device__ __forceinline__ void mma_f16(float* c, const uint32_t* a, const uint32_t* b) {
    asm volatile(
        "mma.sync.aligned.m16n8k16.row.col.f32.f16.f16.f32 "
        "{%0,%1,%2,%3}, {%4,%5,%6,%7}, {%8,%9}, {%0,%1,%2,%3};"
        : "+f"(c[0]), "+f"(c[1]), "+f"(c[2]), "+f"(c[3])
        : "r"(a[0]), "r"(a[1]), "r"(a[2]), "r"(a[3]), "r"(b[0]), "r"(b[1]));
}
__device__ __forceinline__ void ldsm4(uint32_t addr, uint32_t& r0, uint32_t& r1,
                                      uint32_t& r2, uint32_t& r3) {
    asm volatile("ldmatrix.sync.aligned.m8n8.x4.shared.b16 {%0,%1,%2,%3}, [%4];"
                 : "=r"(r0), "=r"(r1), "=r"(r2), "=r"(r3) : "r"(addr));
}

// ---------------- small kernels ----------------------------------------------
__global__ void zero_cnt_kernel() {
    if (threadIdx.x < NE) g_cnt[threadIdx.x] = 0;
}

__global__ void cvt_kernel(const float* __restrict__ in, __half* __restrict__ out, int n4) {
    int i = blockIdx.x * blockDim.x + threadIdx.x;
    int stride = gridDim.x * blockDim.x;
    for (; i < n4; i += stride) {
        float4 v = reinterpret_cast<const float4*>(in)[i];
        __half2 lo = __floats2half2_rn(v.x, v.y);
        __half2 hi = __floats2half2_rn(v.z, v.w);
        uint2 pk = make_uint2(*reinterpret_cast<uint32_t*>(&lo),
                              *reinterpret_cast<uint32_t*>(&hi));
        reinterpret_cast<uint2*>(out)[i] = pk;
    }
}

// [R][C] f32 -> [C][R] f16; 64(R) x 32(C) tiles, half2 stores
__global__ void transcvt_kernel(const float* __restrict__ in, __half* __restrict__ out,
                                int R, int C) {
    __shared__ float tile[32][65];   // [c][r]
    size_t boff = (size_t)blockIdx.z * R * C;
    const float* ib = in + boff;
    __half* ob = out + boff;
    int c0 = blockIdx.x * 32, r0 = blockIdx.y * 64;
    int tx = threadIdx.x, ty = threadIdx.y;
    #pragma unroll
    for (int i = 0; i < 8; i++) {
        int r = ty + 8*i;
        tile[tx][r] = ib[(size_t)(r0 + r) * C + c0 + tx];
    }
    __syncthreads();
    #pragma unroll
    for (int ic = 0; ic < 4; ic++) {
        int c = ty + 8*ic;
        __half2 v = __floats2half2_rn(tile[c][2*tx], tile[c][2*tx+1]);
        *reinterpret_cast<__half2*>(ob + (size_t)(c0 + c) * R + r0 + 2*tx) = v;
    }
}

// ---------------- router ------------------------------------------------------
__global__ void router_kernel(const float* __restrict__ x,
                              const float* __restrict__ gw) {
    int gtid = blockIdx.x * blockDim.x + threadIdx.x;
    int t    = gtid >> 5;
    int lane = gtid & 31;
    if (t >= NT) return;
    const float* xr = x + (size_t)t * NH;

    float acc[8] = {0.f,0.f,0.f,0.f,0.f,0.f,0.f,0.f};
    for (int h = lane; h < NH; h += 32) {
        float xv = __ldg(xr + h);
        const float4* g4 = reinterpret_cast<const float4*>(gw + (size_t)h * 8);
        float4 a = __ldg(g4 + 0);
        float4 b = __ldg(g4 + 1);
        acc[0] = fmaf(xv, a.x, acc[0]); acc[1] = fmaf(xv, a.y, acc[1]);
        acc[2] = fmaf(xv, a.z, acc[2]); acc[3] = fmaf(xv, a.w, acc[3]);
        acc[4] = fmaf(xv, b.x, acc[4]); acc[5] = fmaf(xv, b.y, acc[5]);
        acc[6] = fmaf(xv, b.z, acc[6]); acc[7] = fmaf(xv, b.w, acc[7]);
    }
    #pragma unroll
    for (int e = 0; e < 8; e++)
        #pragma unroll
        for (int off = 16; off > 0; off >>= 1)
            acc[e] += __shfl_xor_sync(0xffffffffu, acc[e], off);
    if (lane == 0) {
        float m = acc[0];
        #pragma unroll
        for (int e = 1; e < 8; e++) m = fmaxf(m, acc[e]);
        float p[8], s = 0.f;
        #pragma unroll
        for (int e = 0; e < 8; e++) { p[e] = expf(acc[e] - m); s += p[e]; }
        float inv = 1.f / s;
        #pragma unroll
        for (int e = 0; e < 8; e++) p[e] *= inv;
        int i0 = 0; float v0 = p[0];
        #pragma unroll
        for (int e = 1; e < 8; e++) if (p[e] > v0) { v0 = p[e]; i0 = e; }
        int i1 = -1; float v1 = -1.f;
        #pragma unroll
        for (int e = 0; e < 8; e++) if (e != i0 && p[e] > v1) { v1 = p[e]; i1 = e; }
        float denom = v0 + v1 + 1e-6f;
        g_w[2*t]   = v0 / denom;
        g_w[2*t+1] = v1 / denom;
        int r0 = atomicAdd(&g_cnt[i0], 1);
        g_rowlist[i0*NT + r0] = t; g_pidlist[i0*NT + r0] = 2*t;
        int r1 = atomicAdd(&g_cnt[i1], 1);
        g_rowlist[i1*NT + r1] = t; g_pidlist[i1*NT + r1] = 2*t + 1;
    }
}

// ---------------- gate+up SwiGLU GEMM (fp16 mma + ldmatrix, frag prefetch) -----
// Block 128(M) x 128(N per matrix). 8 warps, warp tile 64x32 per matrix.
template<bool EXPERT>
__global__ __launch_bounds__(256, 1)
void gateup_mma(const __half* __restrict__ WgT,   // [*, NI, NH] k-contig
                const __half* __restrict__ WuT) {
    extern __shared__ __align__(16) char dsm[];
    const int e    = EXPERT ? blockIdx.z : 0;
    const int M    = EXPERT ? g_cnt[e] : NT;
    const int row0 = blockIdx.y * 128;
    if (row0 >= M) return;
    const int col0 = blockIdx.x * 128;

    const __half* wg = WgT + (EXPERT ? (size_t)e * NI * NH : (size_t)0);
    const __half* wu = WuT + (EXPERT ? (size_t)e * NI * NH : (size_t)0);
    __half* Hout = EXPERT ? (g_hbuf + (size_t)e * NT * NI) : g_shh;

    const int tid = threadIdx.x, wid = tid >> 5, lane = tid & 31;
    const uint32_t sbase = smem_u32(dsm);

    // copy roles
    const __half* s0; const __half* s1;
    uint32_t d0, d1;
    if (tid < 128) {
        int r = tid;
        int li = row0 + r; if (li >= M) li = M - 1;
        int gr = EXPERT ? g_rowlist[e*NT + li] : li;
        s0 = s1 = g_xh + (size_t)gr * NH;
        d0 = d1 = (uint32_t)r * PADH;
    } else if (tid < 192) {
        int u = tid - 128;
        s0 = wg + (size_t)(col0 + u)      * NH;
        s1 = wg + (size_t)(col0 + u + 64) * NH;
        d0 = GU_BG_OFF + (uint32_t)u * PADH;
        d1 = GU_BG_OFF + (uint32_t)(u + 64) * PADH;
    } else {
        int u = tid - 192;
        s0 = wu + (size_t)(col0 + u)      * NH;
        s1 = wu + (size_t)(col0 + u + 64) * NH;
        d0 = GU_BU_OFF + (uint32_t)u * PADH;
        d1 = GU_BU_OFF + (uint32_t)(u + 64) * PADH;
    }
    const bool tworow = (tid >= 128);

    float accg[4][4][4], accu[4][4][4];
    #pragma unroll
    for (int i = 0; i < 4; i++)
        #pragma unroll
        for (int j = 0; j < 4; j++)
            #pragma unroll
            for (int q = 0; q < 4; q++) { accg[i][j][q] = 0.f; accu[i][j][q] = 0.f; }

    const int m0 = (wid & 1) * 64, n0 = (wid >> 1) * 32;
    const int tg = lane >> 2, ti = lane & 3;

    const int q8 = lane >> 3, l7 = lane & 7;
    const uint32_t aoff  = (uint32_t)((m0 + (q8 & 1)*8 + l7) * PADH + (q8 >> 1)*8) * 2;
    const uint32_t bgoff = (uint32_t)(GU_BG_OFF + (n0 + (q8 >> 1)*8 + l7) * PADH + (q8 & 1)*8) * 2;
    const uint32_t buoff = (uint32_t)(GU_BU_OFF + (n0 + (q8 >> 1)*8 + l7) * PADH + (q8 & 1)*8) * 2;

    int koff = 0;
    #pragma unroll
    for (int s = 0; s < NSTAGE - 1; s++) {
        uint32_t base = sbase + (uint32_t)(s * GU_STAGE) * 2;
        #pragma unroll
        for (int c = 0; c < 8; c++) cpa16(base + d0*2 + c*16, s0 + koff + c*8);
        if (tworow) {
            #pragma unroll
            for (int c = 0; c < 8; c++) cpa16(base + d1*2 + c*16, s1 + koff + c*8);
        }
        cp_commit();
        koff += KC;
    }

    uint32_t a[2][4][4], bg[2][4][2], bu[2][4][2];

    const int KST = NH / KC;   // 16
    for (int j = 0; j < KST; j++) {
        if (j < KST - 1) asm volatile("cp.async.wait_group 1;" ::: "memory");
        else             asm volatile("cp.async.wait_group 0;" ::: "memory");
        __syncthreads();
        const uint32_t stg = sbase + (uint32_t)((j % NSTAGE) * GU_STAGE) * 2;

        // prefetch kk=0 fragments; their latency hides under the cp.async burst
        #pragma unroll
        for (int i = 0; i < 4; i++)
            ldsm4(stg + aoff + (uint32_t)(i*16*PADH)*2,
                  a[0][i][0], a[0][i][1], a[0][i][2], a[0][i][3]);
        #pragma unroll
        for (int jp = 0; jp < 2; jp++) {
            ldsm4(stg + bgoff + (uint32_t)(jp*16*PADH)*2,
                  bg[0][2*jp][0], bg[0][2*jp][1], bg[0][2*jp+1][0], bg[0][2*jp+1][1]);
            ldsm4(stg + buoff + (uint32_t)(jp*16*PADH)*2,
                  bu[0][2*jp][0], bu[0][2*jp][1], bu[0][2*jp+1][0], bu[0][2*jp+1][1]);
        }

        if (j + NSTAGE - 1 < KST) {
            int s = (j + NSTAGE - 1) % NSTAGE;
            uint32_t base = sbase + (uint32_t)(s * GU_STAGE) * 2;
            #pragma unroll
            for (int c = 0; c < 8; c++) cpa16(base + d0*2 + c*16, s0 + koff + c*8);
            if (tworow) {
                #pragma unroll
                for (int c = 0; c < 8; c++) cpa16(base + d1*2 + c*16, s1 + koff + c*8);
            }
            cp_commit();
            koff += KC;
        }

        #pragma unroll
        for (int kk = 0; kk < 4; kk++) {
            const int cur = kk & 1, nxt = cur ^ 1;
            if (kk < 3) {
                const uint32_t kb = (uint32_t)((kk+1) * 16) * 2;
                #pragma unroll
                for (int i = 0; i < 4; i++)
                    ldsm4(stg + aoff + (uint32_t)(i*16*PADH)*2 + kb,
                          a[nxt][i][0], a[nxt][i][1], a[nxt][i][2], a[nxt][i][3]);
                #pragma unroll
                for (int jp = 0; jp < 2; jp++) {
                    ldsm4(stg + bgoff + (uint32_t)(jp*16*PADH)*2 + kb,
                          bg[nxt][2*jp][0], bg[nxt][2*jp][1], bg[nxt][2*jp+1][0], bg[nxt][2*jp+1][1]);
                    ldsm4(stg + buoff + (uint32_t)(jp*16*PADH)*2 + kb,
                          bu[nxt][2*jp][0], bu[nxt][2*jp][1], bu[nxt][2*jp+1][0], bu[nxt][2*jp+1][1]);
                }
            }
            #pragma unroll
            for (int jn = 0; jn < 4; jn++)
                #pragma unroll
                for (int i = 0; i < 4; i++) {
                    mma_f16(accg[i][jn], a[cur][i], bg[cur][jn]);
                    mma_f16(accu[i][jn], a[cur][i], bu[cur][jn]);
                }
        }
    }

    // epilogue: silu(g)*u -> fp16
    #pragma unroll
    for (int i = 0; i < 4; i++) {
        #pragma unroll
        for (int half_ = 0; half_ < 2; half_++) {
            int r = m0 + i*16 + half_*8 + tg;
            int lrow = row0 + r;
            if (lrow < M) {
                __half* hrow = Hout + (size_t)lrow * NI + col0 + n0;
                #pragma unroll
                for (int jn = 0; jn < 4; jn++) {
                    float g0 = accg[i][jn][half_*2+0], g1 = accg[i][jn][half_*2+1];
                    float u0 = accu[i][jn][half_*2+0], u1 = accu[i][jn][half_*2+1];
                    float h0 = g0 / (1.f + expf(-g0)) * u0;
                    float h1 = g1 / (1.f + expf(-g1)) * u1;
                    __half2 hv = __floats2half2_rn(h0, h1);
                    *reinterpret_cast<__half2*>(hrow + jn*8 + 2*ti) = hv;
                }
            }
        }
    }
}

// ---------------- down GEMM (fp16 mma + ldmatrix, frag prefetch) ---------------
// Block 128(M) x 256(N). 8 warps, warp tile 64x64.
template<bool EXPERT>
__global__ __launch_bounds__(256, 1)
void down_mma(const __half* __restrict__ WdT,    // [*, NH, NI] k-contig
              float* __restrict__ outp) {
    extern __shared__ __align__(16) char dsm[];
    const int e    = EXPERT ? blockIdx.z : 0;
    const int M    = EXPERT ? g_cnt[e] : NT;
    const int row0 = blockIdx.y * 128;
    if (row0 >= M) return;
    const int col0 = blockIdx.x * 256;

    const __half* A  = EXPERT ? (g_hbuf + (size_t)e * NT * NI) : g_shh;
    const __half* wd = WdT + (EXPERT ? (size_t)e * NH * NI : (size_t)0);

    const int tid = threadIdx.x, wid = tid >> 5, lane = tid & 31;
    const uint32_t sbase = smem_u32(dsm);

    const __half* s0; const __half* s1;
    uint32_t d0, d1;
    if (tid < 128) {
        int r = tid;
        int ar = row0 + r; if (ar >= M) ar = M - 1;
        s0 = s1 = A + (size_t)ar * NI;
        d0 = d1 = (uint32_t)r * PADH;
    } else {
        int u = tid - 128;
        s0 = wd + (size_t)(col0 + u)       * NI;
        s1 = wd + (size_t)(col0 + u + 128) * NI;
        d0 = DN_B_OFF + (uint32_t)u * PADH;
        d1 = DN_B_OFF + (uint32_t)(u + 128) * PADH;
    }
    const bool tworow = (tid >= 128);

    float acc[4][8][4];
    #pragma unroll
    for (int i = 0; i < 4; i++)
        #pragma unroll
        for (int j = 0; j < 8; j++)
            #pragma unroll
            for (int q = 0; q < 4; q++) acc[i][j][q] = 0.f;

    const int m0 = (wid & 1) * 64, n0 = (wid >> 1) * 64;
    const int tg = lane >> 2, ti = lane & 3;

    const int q8 = lane >> 3, l7 = lane & 7;
    const uint32_t aoff = (uint32_t)((m0 + (q8 & 1)*8 + l7) * PADH + (q8 >> 1)*8) * 2;
    const uint32_t boff = (uint32_t)(DN_B_OFF + (n0 + (q8 >> 1)*8 + l7) * PADH + (q8 & 1)*8) * 2;

    int koff = 0;
    #pragma unroll
    for (int s = 0; s < NSTAGE - 1; s++) {
        uint32_t base = sbase + (uint32_t)(s * DN_STAGE) * 2;
        #pragma unroll
        for (int c = 0; c < 8; c++) cpa16(base + d0*2 + c*16, s0 + koff + c*8);
        if (tworow) {
            #pragma unroll
            for (int c = 0; c < 8; c++) cpa16(base + d1*2 + c*16, s1 + koff + c*8);
        }
        cp_commit();
        koff += KC;
    }

    uint32_t a[2][4][4], b[2][8][2];

    const int KST = NI / KC;   // 22
    for (int j = 0; j < KST; j++) {
        if (j < KST - 1) asm volatile("cp.async.wait_group 1;" ::: "memory");
        else             asm volatile("cp.async.wait_group 0;" ::: "memory");
        __syncthreads();
        const uint32_t stg = sbase + (uint32_t)((j % NSTAGE) * DN_STAGE) * 2;

        #pragma unroll
        for (int i = 0; i < 4; i++)
            ldsm4(stg + aoff + (uint32_t)(i*16*PADH)*2,
                  a[0][i][0], a[0][i][1], a[0][i][2], a[0][i][3]);
        #pragma unroll
        for (int jp = 0; jp < 4; jp++)
            ldsm4(stg + boff + (uint32_t)(jp*16*PADH)*2,
                  b[0][2*jp][0], b[0][2*jp][1], b[0][2*jp+1][0], b[0][2*jp+1][1]);

        if (j + NSTAGE - 1 < KST) {
            int s = (j + NSTAGE - 1) % NSTAGE;
            uint32_t base = sbase + (uint32_t)(s * DN_STAGE) * 2;
            #pragma unroll
            for (int c = 0; c < 8; c++) cpa16(base + d0*2 + c*16, s0 + koff + c*8);
            if (tworow) {
                #pragma unroll
                for (int c = 0; c < 8; c++) cpa16(base + d1*2 + c*16, s1 + koff + c*8);
            }
            cp_commit();
            koff += KC;
        }

        #pragma unroll
        for (int kk = 0; kk < 4; kk++) {
            const int cur = kk & 1, nxt = cur ^ 1;
            if (kk < 3) {
                const uint32_t kb = (uint32_t)((kk+1) * 16) * 2;
                #pragma unroll
                for (int i = 0; i < 4; i++)
                    ldsm4(stg + aoff + (uint32_t)(i*16*PADH)*2 + kb,
                          a[nxt][i][0], a[nxt][i][1], a[nxt][i][2], a[nxt][i][3]);
                #pragma unroll
                for (int jp = 0; jp < 4; jp++)
                    ldsm4(stg + boff + (uint32_t)(jp*16*PADH)*2 + kb,
                          b[nxt][2*jp][0], b[nxt][2*jp][1], b[nxt][2*jp+1][0], b[nxt][2*jp+1][1]);
            }
            #pragma unroll
            for (int jn = 0; jn < 8; jn++)
                #pragma unroll
                for (int i = 0; i < 4; i++)
                    mma_f16(acc[i][jn], a[cur][i], b[cur][jn]);
        }
    }

    #pragma unroll
    for (int i = 0; i < 4; i++) {
        #pragma unroll
        for (int half_ = 0; half_ < 2; half_++) {
            int r = m0 + i*16 + half_*8 + tg;
            int lrow = row0 + r;
            if (lrow < M) {
                float* crow;
                if (EXPERT) crow = g_down + (size_t)g_pidlist[e*NT + lrow] * NH;
                else        crow = outp   + (size_t)lrow * NH;
                crow += col0 + n0;
                #pragma unroll
                for (int jn = 0; jn < 8; jn++) {
                    float2 v;
                    v.x = acc[i][jn][half_*2+0];
                    v.y = acc[i][jn][half_*2+1];
                    *reinterpret_cast<float2*>(crow + jn*8 + 2*ti) = v;
                }
            }
        }
    }
}

// ---------------- combine -------------------------------------------------------
__global__ void combine_kernel(float* __restrict__ outp) {
    int t = blockIdx.x;
    int i = threadIdx.x;
    float w0 = g_w[2*t], w1 = g_w[2*t+1];
    float4*       o = reinterpret_cast<float4*>(outp + (size_t)t * NH);
    const float4* a = reinterpret_cast<const float4*>(g_down + (size_t)(2*t)   * NH);
    const float4* b = reinterpret_cast<const float4*>(g_down + (size_t)(2*t+1) * NH);
    float4 ov = o[i], av = a[i], bv = b[i];
    ov.x = fmaf(w1, bv.x, fmaf(w0, av.x, ov.x));
    ov.y = fmaf(w1, bv.y, fmaf(w0, av.y, ov.y));
    ov.z = fmaf(w1, bv.z, fmaf(w0, av.z, ov.z));
    ov.w = fmaf(w1, bv.w, fmaf(w0, av.w, ov.w));
    o[i] = ov;
}

// ---------------- launch ----------------------------------------------------------
extern "C" void kernel_launch(void* const* d_in, const int* in_sizes, int n_in,
                              void* d_out, int out_size) {
    const float* x  = (const float*)d_in[0];
    const float* gw = (const float*)d_in[1];
    const float* eg = (const float*)d_in[2];
    const float* eu = (const float*)d_in[3];
    const float* ed = (const float*)d_in[4];
    const float* sg = (const float*)d_in[5];
    const float* su = (const float*)d_in[6];
    const float* sd = (const float*)d_in[7];
    float* out = (float*)d_out;

    static bool attr_done = false;
    if (!attr_done) {
        cudaFuncSetAttribute(gateup_mma<false>, cudaFuncAttributeMaxDynamicSharedMemorySize, GU_SMEM_BYTES);
        cudaFuncSetAttribute(gateup_mma<true>,  cudaFuncAttributeMaxDynamicSharedMemorySize, GU_SMEM_BYTES);
        cudaFuncSetAttribute(down_mma<false>,   cudaFuncAttributeMaxDynamicSharedMemorySize, DN_SMEM_BYTES);
        cudaFuncSetAttribute(down_mma<true>,    cudaFuncAttributeMaxDynamicSharedMemorySize, DN_SMEM_BYTES);
        attr_done = true;
    }

    __half *p_xh, *p_egT, *p_euT, *p_edT, *p_sgT, *p_suT, *p_sdT;
    cudaGetSymbolAddress((void**)&p_xh,  g_xh);
    cudaGetSymbolAddress((void**)&p_egT, g_egT);
    cudaGetSymbolAddress((void**)&p_euT, g_euT);
    cudaGetSymbolAddress((void**)&p_edT, g_edT);
    cudaGetSymbolAddress((void**)&p_sgT, g_sgT);
    cudaGetSymbolAddress((void**)&p_suT, g_suT);
    cudaGetSymbolAddress((void**)&p_sdT, g_sdT);

    dim3 tb(32, 8);

    // g_cnt is zero on entry (static init on first call; zero_cnt_kernel at the
    // END of each invocation re-arms graph replays). Order makes our launch #5
    // the big expert gateup so ncu (-s 5 -c 1, one harness launch precedes us)
    // lands on a GEMM.
    router_kernel<<<NT/4, 128>>>(x, gw);                                 // 1
    cvt_kernel<<<512, 256>>>(x, p_xh, NT*NH/4);                          // 2
    transcvt_kernel<<<dim3(NI/32, NH/64, NE), tb>>>(eg, p_egT, NH, NI);  // 3
    transcvt_kernel<<<dim3(NI/32, NH/64, NE), tb>>>(eu, p_euT, NH, NI);  // 4
    gateup_mma<true> <<<dim3(NI/128, NT/128, NE), 256, GU_SMEM_BYTES>>>(p_egT, p_euT); // 5 <- profiled
    transcvt_kernel<<<dim3(NI/32, NH/64, 1),  tb>>>(sg, p_sgT, NH, NI);  // 6
    transcvt_kernel<<<dim3(NI/32, NH/64, 1),  tb>>>(su, p_suT, NH, NI);  // 7
    gateup_mma<false><<<dim3(NI/128, NT/128, 1),  256, GU_SMEM_BYTES>>>(p_sgT, p_suT); // 8
    transcvt_kernel<<<dim3(NH/32, NI/64, NE), tb>>>(ed, p_edT, NI, NH);  // 9
    down_mma<true> <<<dim3(NH/256, NT/128, NE), 256, DN_SMEM_BYTES>>>(p_edT, out);     // 10
    transcvt_kernel<<<dim3(NH/32, NI/64, 1),  tb>>>(sd, p_sdT, NI, NH);  // 11
    down_mma<false><<<dim3(NH/256, NT/128, 1),  256, DN_SMEM_BYTES>>>(p_sdT, out);     // 12
    combine_kernel<<<NT, 256>>>(out);                                    // 13
    zero_cnt_kernel<<<1, 32>>>();                                        // 14 (re-arm)
}

// round 13
// speedup vs baseline: 1.0598x; 1.0163x over previous
#include <cuda_runtime.h>
#include <cuda_fp16.h>
#include <math.h>
#include <stdint.h>

// Problem dims (fixed)
#define NT 8192   // tokens
#define NH 1024   // hidden
#define NE 8      // experts
#define NI 1408   // intermediate

#define KC 64     // K halfs per pipeline stage
#define NSTAGE 3
#define PADH 72   // halfs per smem row (144B: ldmatrix row banks conflict-free)

// gateup stage (halfs): A[128][72] + Bg[128][72] + Bu[128][72]
#define GU_BG_OFF (128 * PADH)
#define GU_BU_OFF (256 * PADH)
#define GU_STAGE  (384 * PADH)
#define GU_SMEM_BYTES (NSTAGE * GU_STAGE * 2)        // 165888

// down stage (halfs): A[128][72] + B[256][72]
#define DN_B_OFF  (128 * PADH)
#define DN_STAGE  (384 * PADH)
#define DN_SMEM_BYTES (NSTAGE * DN_STAGE * 2)        // 165888

// ---------------- scratch (device globals) ----------------------------------
__device__ __half g_xh [(size_t)NT*NH];
__device__ __half g_egT[(size_t)NE*NI*NH];       // fp16 weights, [N][K]
__device__ __half g_euT[(size_t)NE*NI*NH];
__device__ __half g_edT[(size_t)NE*NH*NI];
__device__ __half g_sgT[(size_t)NI*NH];
__device__ __half g_suT[(size_t)NI*NH];
__device__ __half g_sdT[(size_t)NH*NI];
__device__ __half g_hbuf[(size_t)NE*NT*NI];
__device__ __half g_shh [(size_t)NT*NI];
__device__ float  g_down[(size_t)2*NT*NH];
__device__ int    g_rowlist[NE*NT];
__device__ int    g_pidlist[NE*NT];
__device__ int    g_cnt[NE];                     // zero at entry; re-zeroed at END
__device__ float  g_w[NT*2];

// ---------------- helpers ----------------------------------------------------
__device__ __forceinline__ uint32_t smem_u32(const void* p) {
    uint32_t a;
    asm("{ .reg .u64 t; cvta.to.shared.u64 t, %1; cvt.u32.u64 %0, t; }" : "=r"(a) : "l"(p));
    return a;
}
__device__ __forceinline__ void cpa16(uint32_t dst, const void* src) {
    asm volatile("cp.async.cg.shared.global [%0], [%1], 16;" :: "r"(dst), "l"(src) : "memory");
}
__device__ __forceinline__ void cp_commit() {
    asm volatile("cp.async.commit_group;" ::: "memory");
}
__device__ __forceinline__ void mma_f16(float* c, const uint32_t* a, const uint32_t* b) {
    asm volatile(
        "mma.sync.aligned.m16n8k16.row.col.f32.f16.f16.f32 "
        "{%0,%1,%2,%3}, {%4,%5,%6,%7}, {%8,%9}, {%0,%1,%2,%3};"
        : "+f"(c[0]), "+f"(c[1]), "+f"(c[2]), "+f"(c[3])
        : "r"(a[0]), "r"(a[1]), "r"(a[2]), "r"(a[3]), "r"(b[0]), "r"(b[1]));
}
__device__ __forceinline__ void ldsm4(uint32_t addr, uint32_t& r0, uint32_t& r1,
                                      uint32_t& r2, uint32_t& r3) {
    asm volatile("ldmatrix.sync.aligned.m8n8.x4.shared.b16 {%0,%1,%2,%3}, [%4];"
                 : "=r"(r0), "=r"(r1), "=r"(r2), "=r"(r3) : "r"(addr));
}

// ---------------- small kernels ----------------------------------------------
__global__ void zero_cnt_kernel() {
    if (threadIdx.x < NE) g_cnt[threadIdx.x] = 0;
}

// ---------------- merged prep: cvt(x) + 6 transpose-converts in ONE grid ------
// Block roles (19520 blocks of (32,8)):
//   [0,512)            : x f32 -> f16 copy
//   [512,6144)         : eg  [NH][NI] -> g_egT [NI][NH]   (44 x 16 x 8)
//   [6144,11776)       : eu  same
//   [11776,17408)      : ed  [NI][NH] -> g_edT [NH][NI]   (32 x 22 x 8)
//   [17408,18112)      : sg  (44 x 16)
//   [18112,18816)      : su
//   [18816,19520)      : sd  (32 x 22)
#define PREP_BLOCKS 19520
__global__ void prep_kernel(const float* __restrict__ x,
                            const float* __restrict__ eg, const float* __restrict__ eu,
                            const float* __restrict__ ed, const float* __restrict__ sg,
                            const float* __restrict__ su, const float* __restrict__ sd) {
    __shared__ float tile[32][65];
    int b = blockIdx.x;
    int tx = threadIdx.x, ty = threadIdx.y;

    if (b < 512) {           // cvt x
        int tid = ty * 32 + tx;
        int n4 = NT * NH / 4;
        for (int i = b * 256 + tid; i < n4; i += 512 * 256) {
            float4 v = reinterpret_cast<const float4*>(x)[i];
            __half2 lo = __floats2half2_rn(v.x, v.y);
            __half2 hi = __floats2half2_rn(v.z, v.w);
            uint2 pk = make_uint2(*reinterpret_cast<uint32_t*>(&lo),
                                  *reinterpret_cast<uint32_t*>(&hi));
            reinterpret_cast<uint2*>(g_xh)[i] = pk;
        }
        return;
    }
    b -= 512;

    const float* in; __half* outp; int R, C, bx, by, bz;
    if (b < 5632) {
        in = eg; outp = g_egT; R = NH; C = NI;
        bz = b / 704; int r = b % 704; bx = r % 44; by = r / 44;
    } else if (b < 11264) {
        b -= 5632; in = eu; outp = g_euT; R = NH; C = NI;
        bz = b / 704; int r = b % 704; bx = r % 44; by = r / 44;
    } else if (b < 16896) {
        b -= 11264; in = ed; outp = g_edT; R = NI; C = NH;
        bz = b / 704; int r = b % 704; bx = r % 32; by = r / 32;
    } else if (b < 17600) {
        b -= 16896; in = sg; outp = g_sgT; R = NH; C = NI;
        bz = 0; bx = b % 44; by = b / 44;
    } else if (b < 18304) {
        b -= 17600; in = su; outp = g_suT; R = NH; C = NI;
        bz = 0; bx = b % 44; by = b / 44;
    } else {
        b -= 18304; in = sd; outp = g_sdT; R = NI; C = NH;
        bz = 0; bx = b % 32; by = b / 32;
    }

    size_t boff = (size_t)bz * R * C;
    const float* ib = in + boff;
    __half* ob = outp + boff;
    int c0 = bx * 32, r0 = by * 64;
    #pragma unroll
    for (int i = 0; i < 8; i++) {
        int r = ty + 8*i;
        tile[tx][r] = ib[(size_t)(r0 + r) * C + c0 + tx];
    }
    __syncthreads();
    #pragma unroll
    for (int ic = 0; ic < 4; ic++) {
        int c = ty + 8*ic;
        __half2 v = __floats2half2_rn(tile[c][2*tx], tile[c][2*tx+1]);
        *reinterpret_cast<__half2*>(ob + (size_t)(c0 + c) * R + r0 + 2*tx) = v;
    }
}

// ---------------- router ------------------------------------------------------
__global__ void router_kernel(const float* __restrict__ x,
                              const float* __restrict__ gw) {
    int gtid = blockIdx.x * blockDim.x + threadIdx.x;
    int t    = gtid >> 5;
    int lane = gtid & 31;
    if (t >= NT) return;
    const float* xr = x + (size_t)t * NH;

    float acc[8] = {0.f,0.f,0.f,0.f,0.f,0.f,0.f,0.f};
    for (int h = lane; h < NH; h += 32) {
        float xv = __ldg(xr + h);
        const float4* g4 = reinterpret_cast<const float4*>(gw + (size_t)h * 8);
        float4 a = __ldg(g4 + 0);
        float4 b = __ldg(g4 + 1);
        acc[0] = fmaf(xv, a.x, acc[0]); acc[1] = fmaf(xv, a.y, acc[1]);
        acc[2] = fmaf(xv, a.z, acc[2]); acc[3] = fmaf(xv, a.w, acc[3]);
        acc[4] = fmaf(xv, b.x, acc[4]); acc[5] = fmaf(xv, b.y, acc[5]);
        acc[6] = fmaf(xv, b.z, acc[6]); acc[7] = fmaf(xv, b.w, acc[7]);
    }
    #pragma unroll
    for (int e = 0; e < 8; e++)
        #pragma unroll
        for (int off = 16; off > 0; off >>= 1)
            acc[e] += __shfl_xor_sync(0xffffffffu, acc[e], off);
    if (lane == 0) {
        float m = acc[0];
        #pragma unroll
        for (int e = 1; e < 8; e++) m = fmaxf(m, acc[e]);
        float p[8], s = 0.f;
        #pragma unroll
        for (int e = 0; e < 8; e++) { p[e] = expf(acc[e] - m); s += p[e]; }
        float inv = 1.f / s;
        #pragma unroll
        for (int e = 0; e < 8; e++) p[e] *= inv;
        int i0 = 0; float v0 = p[0];
        #pragma unroll
        for (int e = 1; e < 8; e++) if (p[e] > v0) { v0 = p[e]; i0 = e; }
        int i1 = -1; float v1 = -1.f;
        #pragma unroll
        for (int e = 0; e < 8; e++) if (e != i0 && p[e] > v1) { v1 = p[e]; i1 = e; }
        float denom = v0 + v1 + 1e-6f;
        g_w[2*t]   = v0 / denom;
        g_w[2*t+1] = v1 / denom;
        int r0 = atomicAdd(&g_cnt[i0], 1);
        g_rowlist[i0*NT + r0] = t; g_pidlist[i0*NT + r0] = 2*t;
        int r1 = atomicAdd(&g_cnt[i1], 1);
        g_rowlist[i1*NT + r1] = t; g_pidlist[i1*NT + r1] = 2*t + 1;
    }
}

// ---------------- gate+up SwiGLU GEMM: one grid for experts + shared -----------
// grid (11, 64, 9): z<8 -> expert z, z==8 -> shared.
// Block 128(M) x 128(N per matrix). 8 warps, warp tile 64x32 per matrix.
__global__ __launch_bounds__(256, 1)
void gateup_all(const __half* __restrict__ egT, const __half* __restrict__ euT,
                const __half* __restrict__ sgT, const __half* __restrict__ suT) {
    extern __shared__ __align__(16) char dsm[];
    const int z = blockIdx.z;
    const bool shexp = (z == NE);
    const int e = shexp ? 0 : z;
    const int M = shexp ? NT : g_cnt[e];
    const int row0 = blockIdx.y * 128;
    if (row0 >= M) return;
    const int col0 = blockIdx.x * 128;

    const __half* wg = shexp ? sgT : egT + (size_t)e * NI * NH;
    const __half* wu = shexp ? suT : euT + (size_t)e * NI * NH;
    __half* Hout = shexp ? g_shh : (g_hbuf + (size_t)e * NT * NI);

    const int tid = threadIdx.x, wid = tid >> 5, lane = tid & 31;
    const uint32_t sbase = smem_u32(dsm);

    const __half* s0; const __half* s1;
    uint32_t d0, d1;
    if (tid < 128) {
        int r = tid;
        int li = row0 + r; if (li >= M) li = M - 1;
        int gr = shexp ? li : g_rowlist[e*NT + li];
        s0 = s1 = g_xh + (size_t)gr * NH;
        d0 = d1 = (uint32_t)r * PADH;
    } else if (tid < 192) {
        int u = tid - 128;
        s0 = wg + (size_t)(col0 + u)      * NH;
        s1 = wg + (size_t)(col0 + u + 64) * NH;
        d0 = GU_BG_OFF + (uint32_t)u * PADH;
        d1 = GU_BG_OFF + (uint32_t)(u + 64) * PADH;
    } else {
        int u = tid - 192;
        s0 = wu + (size_t)(col0 + u)      * NH;
        s1 = wu + (size_t)(col0 + u + 64) * NH;
        d0 = GU_BU_OFF + (uint32_t)u * PADH;
        d1 = GU_BU_OFF + (uint32_t)(u + 64) * PADH;
    }
    const bool tworow = (tid >= 128);

    float accg[4][4][4], accu[4][4][4];
    #pragma unroll
    for (int i = 0; i < 4; i++)
        #pragma unroll
        for (int j = 0; j < 4; j++)
            #pragma unroll
            for (int q = 0; q < 4; q++) { accg[i][j][q] = 0.f; accu[i][j][q] = 0.f; }

    const int m0 = (wid & 1) * 64, n0 = (wid >> 1) * 32;
    const int tg = lane >> 2, ti = lane & 3;

    const int q8 = lane >> 3, l7 = lane & 7;
    const uint32_t aoff  = (uint32_t)((m0 + (q8 & 1)*8 + l7) * PADH + (q8 >> 1)*8) * 2;
    const uint32_t bgoff = (uint32_t)(GU_BG_OFF + (n0 + (q8 >> 1)*8 + l7) * PADH + (q8 & 1)*8) * 2;
    const uint32_t buoff = (uint32_t)(GU_BU_OFF + (n0 + (q8 >> 1)*8 + l7) * PADH + (q8 & 1)*8) * 2;

    int koff = 0;
    #pragma unroll
    for (int s = 0; s < NSTAGE - 1; s++) {
        uint32_t base = sbase + (uint32_t)(s * GU_STAGE) * 2;
        #pragma unroll
        for (int c = 0; c < 8; c++) cpa16(base + d0*2 + c*16, s0 + koff + c*8);
        if (tworow) {
            #pragma unroll
            for (int c = 0; c < 8; c++) cpa16(base + d1*2 + c*16, s1 + koff + c*8);
        }
        cp_commit();
        koff += KC;
    }

    uint32_t a[2][4][4], bg[2][4][2], bu[2][4][2];

    const int KST = NH / KC;   // 16
    for (int j = 0; j < KST; j++) {
        if (j < KST - 1) asm volatile("cp.async.wait_group 1;" ::: "memory");
        else             asm volatile("cp.async.wait_group 0;" ::: "memory");
        __syncthreads();
        const uint32_t stg = sbase + (uint32_t)((j % NSTAGE) * GU_STAGE) * 2;

        #pragma unroll
        for (int i = 0; i < 4; i++)
            ldsm4(stg + aoff + (uint32_t)(i*16*PADH)*2,
                  a[0][i][0], a[0][i][1], a[0][i][2], a[0][i][3]);
        #pragma unroll
        for (int jp = 0; jp < 2; jp++) {
            ldsm4(stg + bgoff + (uint32_t)(jp*16*PADH)*2,
                  bg[0][2*jp][0], bg[0][2*jp][1], bg[0][2*jp+1][0], bg[0][2*jp+1][1]);
            ldsm4(stg + buoff + (uint32_t)(jp*16*PADH)*2,
                  bu[0][2*jp][0], bu[0][2*jp][1], bu[0][2*jp+1][0], bu[0][2*jp+1][1]);
        }

        if (j + NSTAGE - 1 < KST) {
            int s = (j + NSTAGE - 1) % NSTAGE;
            uint32_t base = sbase + (uint32_t)(s * GU_STAGE) * 2;
            #pragma unroll
            for (int c = 0; c < 8; c++) cpa16(base + d0*2 + c*16, s0 + koff + c*8);
            if (tworow) {
                #pragma unroll
                for (int c = 0; c < 8; c++) cpa16(base + d1*2 + c*16, s1 + koff + c*8);
            }
            cp_commit();
            koff += KC;
        }

        #pragma unroll
        for (int kk = 0; kk < 4; kk++) {
            const int cur = kk & 1, nxt = cur ^ 1;
            if (kk < 3) {
                const uint32_t kb = (uint32_t)((kk+1) * 16) * 2;
                #pragma unroll
                for (int i = 0; i < 4; i++)
                    ldsm4(stg + aoff + (uint32_t)(i*16*PADH)*2 + kb,
                          a[nxt][i][0], a[nxt][i][1], a[nxt][i][2], a[nxt][i][3]);
                #pragma unroll
                for (int jp = 0; jp < 2; jp++) {
                    ldsm4(stg + bgoff + (uint32_t)(jp*16*PADH)*2 + kb,
                          bg[nxt][2*jp][0], bg[nxt][2*jp][1], bg[nxt][2*jp+1][0], bg[nxt][2*jp+1][1]);
                    ldsm4(stg + buoff + (uint32_t)(jp*16*PADH)*2 + kb,
                          bu[nxt][2*jp][0], bu[nxt][2*jp][1], bu[nxt][2*jp+1][0], bu[nxt][2*jp+1][1]);
                }
            }
            #pragma unroll
            for (int jn = 0; jn < 4; jn++)
                #pragma unroll
                for (int i = 0; i < 4; i++) {
                    mma_f16(accg[i][jn], a[cur][i], bg[cur][jn]);
                    mma_f16(accu[i][jn], a[cur][i], bu[cur][jn]);
                }
        }
    }

    #pragma unroll
    for (int i = 0; i < 4; i++) {
        #pragma unroll
        for (int half_ = 0; half_ < 2; half_++) {
            int r = m0 + i*16 + half_*8 + tg;
            int lrow = row0 + r;
            if (lrow < M) {
                __half* hrow = Hout + (size_t)lrow * NI + col0 + n0;
                #pragma unroll
                for (int jn = 0; jn < 4; jn++) {
                    float g0 = accg[i][jn][half_*2+0], g1 = accg[i][jn][half_*2+1];
                    float u0 = accu[i][jn][half_*2+0], u1 = accu[i][jn][half_*2+1];
                    float h0 = g0 / (1.f + expf(-g0)) * u0;
                    float h1 = g1 / (1.f + expf(-g1)) * u1;
                    __half2 hv = __floats2half2_rn(h0, h1);
                    *reinterpret_cast<__half2*>(hrow + jn*8 + 2*ti) = hv;
                }
            }
        }
    }
}

// ---------------- down GEMM: one grid for experts + shared ---------------------
// grid (4, 64, 9): z<8 -> expert z (scatter to g_down), z==8 -> shared (direct).
// Block 128(M) x 256(N). 8 warps, warp tile 64x64.
__global__ __launch_bounds__(256, 1)
void down_all(const __half* __restrict__ edT, const __half* __restrict__ sdT,
              float* __restrict__ outp) {
    extern __shared__ __align__(16) char dsm[];
    const int z = blockIdx.z;
    const bool shexp = (z == NE);
    const int e = shexp ? 0 : z;
    const int M = shexp ? NT : g_cnt[e];
    const int row0 = blockIdx.y * 128;
    if (row0 >= M) return;
    const int col0 = blockIdx.x * 256;

    const __half* A  = shexp ? g_shh : (g_hbuf + (size_t)e * NT * NI);
    const __half* wd = shexp ? sdT : edT + (size_t)e * NH * NI;

    const int tid = threadIdx.x, wid = tid >> 5, lane = tid & 31;
    const uint32_t sbase = smem_u32(dsm);

    const __half* s0; const __half* s1;
    uint32_t d0, d1;
    if (tid < 128) {
        int r = tid;
        int ar = row0 + r; if (ar >= M) ar = M - 1;
        s0 = s1 = A + (size_t)ar * NI;
        d0 = d1 = (uint32_t)r * PADH;
    } else {
        int u = tid - 128;
        s0 = wd + (size_t)(col0 + u)       * NI;
        s1 = wd + (size_t)(col0 + u + 128) * NI;
        d0 = DN_B_OFF + (uint32_t)u * PADH;
        d1 = DN_B_OFF + (uint32_t)(u + 128) * PADH;
    }
    const bool tworow = (tid >= 128);

    float acc[4][8][4];
    #pragma unroll
    for (int i = 0; i < 4; i++)
        #pragma unroll
        for (int j = 0; j < 8; j++)
            #pragma unroll
            for (int q = 0; q < 4; q++) acc[i][j][q] = 0.f;

    const int m0 = (wid & 1) * 64, n0 = (wid >> 1) * 64;
    const int tg = lane >> 2, ti = lane & 3;

    const int q8 = lane >> 3, l7 = lane & 7;
    const uint32_t aoff = (uint32_t)((m0 + (q8 & 1)*8 + l7) * PADH + (q8 >> 1)*8) * 2;
    const uint32_t boff = (uint32_t)(DN_B_OFF + (n0 + (q8 >> 1)*8 + l7) * PADH + (q8 & 1)*8) * 2;

    int koff = 0;
    #pragma unroll
    for (int s = 0; s < NSTAGE - 1; s++) {
        uint32_t base = sbase + (uint32_t)(s * DN_STAGE) * 2;
        #pragma unroll
        for (int c = 0; c < 8; c++) cpa16(base + d0*2 + c*16, s0 + koff + c*8);
        if (tworow) {
            #pragma unroll
            for (int c = 0; c < 8; c++) cpa16(base + d1*2 + c*16, s1 + koff + c*8);
        }
        cp_commit();
        koff += KC;
    }

    uint32_t a[2][4][4], b[2][8][2];

    const int KST = NI / KC;   // 22
    for (int j = 0; j < KST; j++) {
        if (j < KST - 1) asm volatile("cp.async.wait_group 1;" ::: "memory");
        else             asm volatile("cp.async.wait_group 0;" ::: "memory");
        __syncthreads();
        const uint32_t stg = sbase + (uint32_t)((j % NSTAGE) * DN_STAGE) * 2;

        #pragma unroll
        for (int i = 0; i < 4; i++)
            ldsm4(stg + aoff + (uint32_t)(i*16*PADH)*2,
                  a[0][i][0], a[0][i][1], a[0][i][2], a[0][i][3]);
        #pragma unroll
        for (int jp = 0; jp < 4; jp++)
            ldsm4(stg + boff + (uint32_t)(jp*16*PADH)*2,
                  b[0][2*jp][0], b[0][2*jp][1], b[0][2*jp+1][0], b[0][2*jp+1][1]);

        if (j + NSTAGE - 1 < KST) {
            int s = (j + NSTAGE - 1) % NSTAGE;
            uint32_t base = sbase + (uint32_t)(s * DN_STAGE) * 2;
            #pragma unroll
            for (int c = 0; c < 8; c++) cpa16(base + d0*2 + c*16, s0 + koff + c*8);
            if (tworow) {
                #pragma unroll
                for (int c = 0; c < 8; c++) cpa16(base + d1*2 + c*16, s1 + koff + c*8);
            }
            cp_commit();
            koff += KC;
        }

        #pragma unroll
        for (int kk = 0; kk < 4; kk++) {
            const int cur = kk & 1, nxt = cur ^ 1;
            if (kk < 3) {
                const uint32_t kb = (uint32_t)((kk+1) * 16) * 2;
                #pragma unroll
                for (int i = 0; i < 4; i++)
                    ldsm4(stg + aoff + (uint32_t)(i*16*PADH)*2 + kb,
                          a[nxt][i][0], a[nxt][i][1], a[nxt][i][2], a[nxt][i][3]);
                #pragma unroll
                for (int jp = 0; jp < 4; jp++)
                    ldsm4(stg + boff + (uint32_t)(jp*16*PADH)*2 + kb,
                          b[nxt][2*jp][0], b[nxt][2*jp][1], b[nxt][2*jp+1][0], b[nxt][2*jp+1][1]);
            }
            #pragma unroll
            for (int jn = 0; jn < 8; jn++)
                #pragma unroll
                for (int i = 0; i < 4; i++)
                    mma_f16(acc[i][jn], a[cur][i], b[cur][jn]);
        }
    }

    #pragma unroll
    for (int i = 0; i < 4; i++) {
        #pragma unroll
        for (int half_ = 0; half_ < 2; half_++) {
            int r = m0 + i*16 + half_*8 + tg;
            int lrow = row0 + r;
            if (lrow < M) {
                float* crow;
                if (!shexp) crow = g_down + (size_t)g_pidlist[e*NT + lrow] * NH;
                else        crow = outp   + (size_t)lrow * NH;
                crow += col0 + n0;
                #pragma unroll
                for (int jn = 0; jn < 8; jn++) {
                    float2 v;
                    v.x = acc[i][jn][half_*2+0];
                    v.y = acc[i][jn][half_*2+1];
                    *reinterpret_cast<float2*>(crow + jn*8 + 2*ti) = v;
                }
            }
        }
    }
}

// ---------------- combine -------------------------------------------------------
__global__ void combine_kernel(float* __restrict__ outp) {
    int t = blockIdx.x;
    int i = threadIdx.x;
    float w0 = g_w[2*t], w1 = g_w[2*t+1];
    float4*       o = reinterpret_cast<float4*>(outp + (size_t)t * NH);
    const float4* a = reinterpret_cast<const float4*>(g_down + (size_t)(2*t)   * NH);
    const float4* b = reinterpret_cast<const float4*>(g_down + (size_t)(2*t+1) * NH);
    float4 ov = o[i], av = a[i], bv = b[i];
    ov.x = fmaf(w1, bv.x, fmaf(w0, av.x, ov.x));
    ov.y = fmaf(w1, bv.y, fmaf(w0, av.y, ov.y));
    ov.z = fmaf(w1, bv.z, fmaf(w0, av.z, ov.z));
    ov.w = fmaf(w1, bv.w, fmaf(w0, av.w, ov.w));
    o[i] = ov;
}

// ---------------- launch ----------------------------------------------------------
extern "C" void kernel_launch(void* const* d_in, const int* in_sizes, int n_in,
                              void* d_out, int out_size) {
    const float* x  = (const float*)d_in[0];
    const float* gw = (const float*)d_in[1];
    const float* eg = (const float*)d_in[2];
    const float* eu = (const float*)d_in[3];
    const float* ed = (const float*)d_in[4];
    const float* sg = (const float*)d_in[5];
    const float* su = (const float*)d_in[6];
    const float* sd = (const float*)d_in[7];
    float* out = (float*)d_out;

    static bool attr_done = false;
    if (!attr_done) {
        cudaFuncSetAttribute(gateup_all, cudaFuncAttributeMaxDynamicSharedMemorySize, GU_SMEM_BYTES);
        cudaFuncSetAttribute(down_all,   cudaFuncAttributeMaxDynamicSharedMemorySize, DN_SMEM_BYTES);
        attr_done = true;
    }

    __half *p_egT, *p_euT, *p_edT, *p_sgT, *p_suT, *p_sdT;
    cudaGetSymbolAddress((void**)&p_egT, g_egT);
    cudaGetSymbolAddress((void**)&p_euT, g_euT);
    cudaGetSymbolAddress((void**)&p_edT, g_edT);
    cudaGetSymbolAddress((void**)&p_sgT, g_sgT);
    cudaGetSymbolAddress((void**)&p_suT, g_suT);
    cudaGetSymbolAddress((void**)&p_sdT, g_sdT);

    // g_cnt is zero on entry (static zero-init on first call; zero_cnt_kernel
    // at the END of each invocation re-arms graph replays).
    router_kernel<<<NT/4, 128>>>(x, gw);                                   // 1
    prep_kernel<<<PREP_BLOCKS, dim3(32, 8)>>>(x, eg, eu, ed, sg, su, sd);  // 2
    gateup_all<<<dim3(NI/128, NT/128, NE+1), 256, GU_SMEM_BYTES>>>(p_egT, p_euT, p_sgT, p_suT); // 3
    down_all  <<<dim3(NH/256, NT/128, NE+1), 256, DN_SMEM_BYTES>>>(p_edT, p_sdT, out);          // 4
    combine_kernel<<<NT, 256>>>(out);                                      // 5
    zero_cnt_kernel<<<1, 32>>>();                                          // 6 (re-arm)
}